// round 1
// baseline (speedup 1.0000x reference)
#include <cuda_runtime.h>
#include <math.h>

#define Bv   2
#define Lv   2048
#define DM   512
#define DI   1024
#define DS   16
#define DCV  4
#define DTR  32
#define ROWS (Bv * Lv)      // 4096
#define XPN  (DTR + 2*DS)   // 64

// ---------------- scratch (static device allocations) ----------------
__device__ float g_xz [ROWS * 2 * DI];   // in_proj output (xi | z)
__device__ float g_xc [ROWS * DI];       // conv+silu output
__device__ float g_dbc[ROWS * XPN];      // xproj output (dt_raw | B | C)
__device__ float g_dt [ROWS * DI];       // softplus(dt)
__device__ float g_ys [ROWS * DI];       // scan output (pre out_proj)
__device__ float g_od [2 * ROWS * DM];   // per-direction out_proj results

__device__ __forceinline__ float silu_f(float x) { return x / (1.f + __expf(-x)); }

// ---------------- generic tiled fp32 GEMM ----------------
// C[M,N] = op(A)[M,K] @ W[K,N] (+bias) (+=C if acc)
// revA: read A rows L-reversed per batch; revC: write C rows L-reversed per batch.
__global__ void gemm64(const float* __restrict__ A, const float* __restrict__ W,
                       const float* __restrict__ bias, float* __restrict__ C,
                       int M, int N, int K, int revA, int revC, int acc)
{
    __shared__ float As[16][65];
    __shared__ float Ws[16][65];
    const int tid = threadIdx.x;
    const int tx = tid & 15, ty = tid >> 4;
    const int m0 = blockIdx.y * 64, n0 = blockIdx.x * 64;

    float accv[4][4];
#pragma unroll
    for (int i = 0; i < 4; i++)
#pragma unroll
        for (int j = 0; j < 4; j++) accv[i][j] = 0.f;

    // A tile loader: thread -> (row=tid/4, k-quad=(tid&3)*4)
    const int ar  = tid >> 2;
    const int akq = (tid & 3) * 4;
    int arow = m0 + ar;
    if (revA) { int b = arow / Lv, l = arow % Lv; arow = b * Lv + (Lv - 1 - l); }
    const float* Aptr = A + (long)arow * K + akq;

    // W tile loader: thread -> (k=tid/16, col-quad=(tid&15)*4)
    const int wk = tid >> 4;
    const int wc = (tid & 15) * 4;
    const float* Wptr = W + (long)wk * N + n0 + wc;

    for (int kb = 0; kb < K; kb += 16) {
        float4 av = *(const float4*)(Aptr + kb);
        As[akq + 0][ar] = av.x; As[akq + 1][ar] = av.y;
        As[akq + 2][ar] = av.z; As[akq + 3][ar] = av.w;
        float4 wv = *(const float4*)(Wptr + (long)kb * N);
        Ws[wk][wc + 0] = wv.x; Ws[wk][wc + 1] = wv.y;
        Ws[wk][wc + 2] = wv.z; Ws[wk][wc + 3] = wv.w;
        __syncthreads();
#pragma unroll
        for (int kk = 0; kk < 16; kk++) {
            float a[4], w[4];
#pragma unroll
            for (int i = 0; i < 4; i++) a[i] = As[kk][ty + 16 * i];
#pragma unroll
            for (int j = 0; j < 4; j++) w[j] = Ws[kk][tx + 16 * j];
#pragma unroll
            for (int i = 0; i < 4; i++)
#pragma unroll
                for (int j = 0; j < 4; j++)
                    accv[i][j] = fmaf(a[i], w[j], accv[i][j]);
        }
        __syncthreads();
    }

#pragma unroll
    for (int i = 0; i < 4; i++) {
        int row = m0 + ty + 16 * i;
        int grow = row;
        if (revC) { int b = row / Lv, l = row % Lv; grow = b * Lv + (Lv - 1 - l); }
#pragma unroll
        for (int j = 0; j < 4; j++) {
            int col = n0 + tx + 16 * j;
            float v = accv[i][j];
            if (bias) v += bias[col];
            if (acc)  v += C[(long)grow * N + col];
            C[(long)grow * N + col] = v;
        }
    }
}

// ---------------- depthwise causal conv (width 4) + SiLU ----------------
__global__ void conv_silu_kernel(const float* __restrict__ xz,
                                 const float* __restrict__ cw,
                                 const float* __restrict__ cb,
                                 float* __restrict__ xc)
{
    int idx = blockIdx.x * blockDim.x + threadIdx.x;
    if (idx >= ROWS * DI) return;
    int d   = idx & (DI - 1);
    int row = idx >> 10;          // DI = 1024
    int l   = row & (Lv - 1);     // Lv = 2048
    float s = cb[d];
    float w0 = cw[d * 4 + 0], w1 = cw[d * 4 + 1],
          w2 = cw[d * 4 + 2], w3 = cw[d * 4 + 3];
    const float* xp = xz + (long)row * (2 * DI) + d;
    if (l >= 3) s = fmaf(w0, xp[-3 * 2 * DI], s);
    if (l >= 2) s = fmaf(w1, xp[-2 * 2 * DI], s);
    if (l >= 1) s = fmaf(w2, xp[-1 * 2 * DI], s);
    s = fmaf(w3, xp[0], s);
    xc[idx] = silu_f(s);
}

// ---------------- dt projection (K=32) + softplus, weight tile in smem ----------------
__global__ void dtproj_kernel(const float* __restrict__ dbc,
                              const float* __restrict__ dtw,
                              const float* __restrict__ dtb,
                              float* __restrict__ dt)
{
    __shared__ float wtile[DTR][256];
    __shared__ float rbuf[DTR];
    int d = blockIdx.x * 256 + threadIdx.x;
    // per-thread column of weights (read only by this thread -> no sync needed)
#pragma unroll
    for (int k = 0; k < DTR; k++) wtile[k][threadIdx.x] = dtw[k * DI + d];
    float bvv = dtb[d];
    int row0 = blockIdx.y * 128;
    for (int r = 0; r < 128; r++) {
        int row = row0 + r;
        __syncthreads();
        if (threadIdx.x < DTR) rbuf[threadIdx.x] = dbc[row * XPN + threadIdx.x];
        __syncthreads();
        float s = bvv;
#pragma unroll
        for (int k = 0; k < DTR; k++) s = fmaf(rbuf[k], wtile[k][threadIdx.x], s);
        dt[(long)row * DI + d] = (s > 20.f) ? s : log1pf(__expf(s));
    }
}

// ---------------- selective scan: 16 lanes = 16 states per (b,d) ----------------
__global__ void scan_kernel(const float* __restrict__ dt,
                            const float* __restrict__ xc,
                            const float* __restrict__ dbc,
                            const float* __restrict__ xz,
                            const float* __restrict__ A_log,
                            const float* __restrict__ Dskip,
                            float* __restrict__ ys)
{
    int t = blockIdx.x * blockDim.x + threadIdx.x;
    int gid = t >> 4;
    int n = t & 15;
    if (gid >= Bv * DI) return;
    int b = gid / DI, d = gid % DI;

    float An = -__expf(A_log[d * DS + n]);
    float Dd = Dskip[d];

    const float* dtp = dt  + (long)b * Lv * DI + d;
    const float* xcp = xc  + (long)b * Lv * DI + d;
    const float* dbp = dbc + (long)b * Lv * XPN;
    const float* zp  = xz  + (long)b * Lv * (2 * DI) + DI + d;
    float* yp        = ys  + (long)b * Lv * DI + d;

    float h = 0.f;
    // prefetch l = 0
    float dtv = dtp[0], xcv = xcp[0];
    float Bn = dbp[DTR + n], Cn = dbp[DTR + DS + n];
    float zv = zp[0];

    for (int l = 0; l < Lv; l++) {
        float dt2 = 0.f, xc2 = 0.f, B2 = 0.f, C2 = 0.f, z2 = 0.f;
        if (l + 1 < Lv) {
            dt2 = dtp[(l + 1) * DI];
            xc2 = xcp[(l + 1) * DI];
            B2  = dbp[(l + 1) * XPN + DTR + n];
            C2  = dbp[(l + 1) * XPN + DTR + DS + n];
            z2  = zp[(l + 1) * 2 * DI];
        }
        float dA = __expf(dtv * An);
        h = fmaf(dA, h, dtv * xcv * Bn);
        float p = h * Cn;
        p += __shfl_xor_sync(0xffffffffu, p, 8);
        p += __shfl_xor_sync(0xffffffffu, p, 4);
        p += __shfl_xor_sync(0xffffffffu, p, 2);
        p += __shfl_xor_sync(0xffffffffu, p, 1);
        if (n == 0) {
            float y = p + xcv * Dd;
            y *= silu_f(zv);
            yp[l * DI] = y;
        }
        dtv = dt2; xcv = xc2; Bn = B2; Cn = C2; zv = z2;
    }
}

// ---------------- launch ----------------
extern "C" void kernel_launch(void* const* d_in, const int* in_sizes, int n_in,
                              void* d_out, int out_size)
{
    const float* hidden = (const float*)d_in[0];
    float* out = (float*)d_out;

    float *xz, *xc, *dbc, *dtb_buf, *ys, *od;
    cudaGetSymbolAddress((void**)&xz,      g_xz);
    cudaGetSymbolAddress((void**)&xc,      g_xc);
    cudaGetSymbolAddress((void**)&dbc,     g_dbc);
    cudaGetSymbolAddress((void**)&dtb_buf, g_dt);
    cudaGetSymbolAddress((void**)&ys,      g_ys);
    cudaGetSymbolAddress((void**)&od,      g_od);

    for (int dir = 0; dir < 2; dir++) {
        const int o = 1 + 9 * dir;
        const float* in_w    = (const float*)d_in[o + 0];
        const float* conv_w  = (const float*)d_in[o + 1];
        const float* conv_b  = (const float*)d_in[o + 2];
        const float* xproj_w = (const float*)d_in[o + 3];
        const float* dt_w    = (const float*)d_in[o + 4];
        const float* dt_b    = (const float*)d_in[o + 5];
        const float* A_log   = (const float*)d_in[o + 6];
        const float* D_skip  = (const float*)d_in[o + 7];
        const float* out_w   = (const float*)d_in[o + 8];

        // 1. in_proj: (4096,512) @ (512,2048) -> xz   (bwd: read rows L-reversed)
        gemm64<<<dim3(2048 / 64, ROWS / 64), 256>>>(
            hidden, in_w, nullptr, xz, ROWS, 2 * DI, DM, dir, 0, 0);

        // 2. causal conv + silu -> xc
        conv_silu_kernel<<<(ROWS * DI) / 256, 256>>>(xz, conv_w, conv_b, xc);

        // 3. xproj: (4096,1024) @ (1024,64) -> dbc
        gemm64<<<dim3(XPN / 64, ROWS / 64), 256>>>(
            xc, xproj_w, nullptr, dbc, ROWS, XPN, DI, 0, 0, 0);

        // 4. dt proj + softplus -> dt
        dtproj_kernel<<<dim3(DI / 256, ROWS / 128), 256>>>(dbc, dt_w, dt_b, dtb_buf);

        // 5. selective scan -> ys
        scan_kernel<<<(Bv * DI * 16) / 256, 256>>>(
            dtb_buf, xc, dbc, xz, A_log, D_skip, ys);

        // 6. out_proj: (4096,1024) @ (1024,512) -> od[dir]  (bwd: write rows L-reversed)
        gemm64<<<dim3(DM / 64, ROWS / 64), 256>>>(
            ys, out_w, nullptr, od + (long)dir * ROWS * DM, ROWS, DM, DI, 0, dir, 0);
    }

    const float* fuse_w = (const float*)d_in[19];
    const float* fuse_b = (const float*)d_in[20];

    // fuse: out = od_fwd @ fuse_w[:512] + od_bwd @ fuse_w[512:] + fuse_b
    gemm64<<<dim3(DM / 64, ROWS / 64), 256>>>(
        od, fuse_w, fuse_b, out, ROWS, DM, DM, 0, 0, 0);
    gemm64<<<dim3(DM / 64, ROWS / 64), 256>>>(
        od + (long)ROWS * DM, fuse_w + (long)DM * DM, nullptr, out, ROWS, DM, DM, 0, 0, 1);
}

// round 2
// speedup vs baseline: 1.1425x; 1.1425x over previous
#include <cuda_runtime.h>
#include <math.h>

#define Bv   2
#define Lv   2048
#define DM   512
#define DI   1024
#define DS   16
#define DTR  32
#define ROWS (Bv * Lv)      // 4096
#define XPN  (DTR + 2*DS)   // 64

// ---------------- scratch ----------------
__device__ float g_xz [ROWS * 2 * DI];   // in_proj output (xi | z)
__device__ float g_xc [ROWS * DI];       // conv+silu output
__device__ float g_dbc[ROWS * XPN];      // xproj output (dt_raw | B | C)
__device__ float g_dt [ROWS * DI];       // softplus(dt)
__device__ float g_ys [ROWS * DI];       // scan output
__device__ float g_od [ROWS * 2 * DM];   // out_proj results interleaved: [row][dir*512+col]

__device__ __forceinline__ float silu_f(float x) { return x / (1.f + __expf(-x)); }

// ================= 128xBN double-buffered fp32 GEMM =================
// C[M,N] = op(A)[M,K] @ W[K,N] (+bias) (softplus epilogue if SOFTPLUS)
// A row-major with leading dim lda; C with leading dim ldc.
// revA: read A rows L-reversed per batch of 2048; revC: write reversed.
template<int BN, int TN, int SOFTPLUS>
__global__ __launch_bounds__(256, 2)
void gemmT(const float* __restrict__ A, const float* __restrict__ W,
           const float* __restrict__ bias, float* __restrict__ C,
           int N, int K, int lda, int ldc, int revA, int revC)
{
    constexpr int BM = 128;
    __shared__ float As[2][16][BM + 4];
    __shared__ float Ws[2][16][BN + 4];

    const int tid = threadIdx.x;
    const int tx = tid & 15, ty = tid >> 4;
    const long m0 = (long)blockIdx.y * BM;
    const int n0 = blockIdx.x * BN;

    // ---- A tile loader: 2 float4 per thread ----
    const int ar  = tid >> 2;            // 0..63
    const int akq = (tid & 3) * 4;       // k quad
    long arow0 = m0 + ar, arow1 = m0 + ar + 64;
    if (revA) {
        long b0 = arow0 >> 11, l0 = arow0 & 2047; arow0 = (b0 << 11) + (2047 - l0);
        long b1 = arow1 >> 11, l1 = arow1 & 2047; arow1 = (b1 << 11) + (2047 - l1);
    }
    const float* Ap0 = A + arow0 * lda + akq;
    const float* Ap1 = A + arow1 * lda + akq;

    // ---- W tile loader ----
    int wk0, wc0, wk1 = 0;
    const float *Wp0, *Wp1 = nullptr;
    if (BN == 128) {
        wk0 = tid >> 5; wc0 = (tid & 31) * 4; wk1 = wk0 + 8;
        Wp0 = W + (long)wk0 * N + n0 + wc0;
        Wp1 = W + (long)wk1 * N + n0 + wc0;
    } else { // BN == 64
        wk0 = tid >> 4; wc0 = (tid & 15) * 4;
        Wp0 = W + (long)wk0 * N + n0 + wc0;
    }

    float acc[8][TN];
#pragma unroll
    for (int i = 0; i < 8; i++)
#pragma unroll
        for (int j = 0; j < TN; j++) acc[i][j] = 0.f;

    const int nb = K >> 4;

    // preload k-block 0
    float4 pa0 = *(const float4*)Ap0;
    float4 pa1 = *(const float4*)Ap1;
    float4 pw0 = *(const float4*)Wp0;
    float4 pw1 = (BN == 128) ? *(const float4*)Wp1 : make_float4(0,0,0,0);

    As[0][akq + 0][ar] = pa0.x; As[0][akq + 1][ar] = pa0.y;
    As[0][akq + 2][ar] = pa0.z; As[0][akq + 3][ar] = pa0.w;
    As[0][akq + 0][ar + 64] = pa1.x; As[0][akq + 1][ar + 64] = pa1.y;
    As[0][akq + 2][ar + 64] = pa1.z; As[0][akq + 3][ar + 64] = pa1.w;
    *(float4*)&Ws[0][wk0][wc0] = pw0;
    if (BN == 128) *(float4*)&Ws[0][wk1][wc0] = pw1;
    __syncthreads();

    for (int kb = 0; kb < nb; kb++) {
        const int cur = kb & 1;
        if (kb + 1 < nb) {
            const int ko = (kb + 1) * 16;
            pa0 = *(const float4*)(Ap0 + ko);
            pa1 = *(const float4*)(Ap1 + ko);
            pw0 = *(const float4*)(Wp0 + (long)ko * N);
            if (BN == 128) pw1 = *(const float4*)(Wp1 + (long)ko * N);
        }
#pragma unroll
        for (int kk = 0; kk < 16; kk++) {
            float4 a0 = *(const float4*)&As[cur][kk][ty * 4];
            float4 a1 = *(const float4*)&As[cur][kk][64 + ty * 4];
            float4 b0 = *(const float4*)&Ws[cur][kk][tx * 4];
            float av[8] = {a0.x, a0.y, a0.z, a0.w, a1.x, a1.y, a1.z, a1.w};
            float bvv[TN];
            bvv[0] = b0.x; bvv[1] = b0.y; bvv[2] = b0.z; bvv[3] = b0.w;
            if (TN == 8) {
                float4 b1 = *(const float4*)&Ws[cur][kk][64 + tx * 4];
                bvv[4] = b1.x; bvv[5] = b1.y; bvv[6] = b1.z; bvv[7] = b1.w;
            }
#pragma unroll
            for (int i = 0; i < 8; i++)
#pragma unroll
                for (int j = 0; j < TN; j++)
                    acc[i][j] = fmaf(av[i], bvv[j], acc[i][j]);
        }
        if (kb + 1 < nb) {
            const int nxt = cur ^ 1;
            As[nxt][akq + 0][ar] = pa0.x; As[nxt][akq + 1][ar] = pa0.y;
            As[nxt][akq + 2][ar] = pa0.z; As[nxt][akq + 3][ar] = pa0.w;
            As[nxt][akq + 0][ar + 64] = pa1.x; As[nxt][akq + 1][ar + 64] = pa1.y;
            As[nxt][akq + 2][ar + 64] = pa1.z; As[nxt][akq + 3][ar + 64] = pa1.w;
            *(float4*)&Ws[nxt][wk0][wc0] = pw0;
            if (BN == 128) *(float4*)&Ws[nxt][wk1][wc0] = pw1;
            __syncthreads();
        }
    }

    // ---- epilogue ----
#pragma unroll
    for (int c = 0; c < 2; c++) {
#pragma unroll
        for (int i = 0; i < 4; i++) {
            long row = m0 + c * 64 + ty * 4 + i;
            long grow = row;
            if (revC) { long b = row >> 11, l = row & 2047; grow = (b << 11) + (2047 - l); }
            float* Crow = C + grow * ldc + n0;
#pragma unroll
            for (int jc = 0; jc < TN / 4; jc++) {
                float4 v;
                float* a = &acc[c * 4 + i][jc * 4];
                v.x = a[0]; v.y = a[1]; v.z = a[2]; v.w = a[3];
                if (bias) {
                    const float* bp = bias + n0 + jc * 64 + tx * 4;
                    v.x += bp[0]; v.y += bp[1]; v.z += bp[2]; v.w += bp[3];
                }
                if (SOFTPLUS) {
                    v.x = (v.x > 20.f) ? v.x : log1pf(__expf(v.x));
                    v.y = (v.y > 20.f) ? v.y : log1pf(__expf(v.y));
                    v.z = (v.z > 20.f) ? v.z : log1pf(__expf(v.z));
                    v.w = (v.w > 20.f) ? v.w : log1pf(__expf(v.w));
                }
                *(float4*)(Crow + jc * 64 + tx * 4) = v;
            }
        }
    }
}

// ---------------- depthwise causal conv (width 4) + SiLU ----------------
__global__ void conv_silu_kernel(const float* __restrict__ xz,
                                 const float* __restrict__ cw,
                                 const float* __restrict__ cb,
                                 float* __restrict__ xc)
{
    int idx = blockIdx.x * blockDim.x + threadIdx.x;
    if (idx >= ROWS * DI) return;
    int d   = idx & (DI - 1);
    int row = idx >> 10;
    int l   = row & (Lv - 1);
    float s = cb[d];
    float w0 = cw[d * 4 + 0], w1 = cw[d * 4 + 1],
          w2 = cw[d * 4 + 2], w3 = cw[d * 4 + 3];
    const float* xp = xz + (long)row * (2 * DI) + d;
    if (l >= 3) s = fmaf(w0, xp[-3 * 2 * DI], s);
    if (l >= 2) s = fmaf(w1, xp[-2 * 2 * DI], s);
    if (l >= 1) s = fmaf(w2, xp[-1 * 2 * DI], s);
    s = fmaf(w3, xp[0], s);
    xc[idx] = silu_f(s);
}

// ---------------- selective scan ----------------
__global__ void scan_kernel(const float* __restrict__ dt,
                            const float* __restrict__ xc,
                            const float* __restrict__ dbc,
                            const float* __restrict__ xz,
                            const float* __restrict__ A_log,
                            const float* __restrict__ Dskip,
                            float* __restrict__ ys)
{
    int t = blockIdx.x * blockDim.x + threadIdx.x;
    int gid = t >> 4;
    int n = t & 15;
    if (gid >= Bv * DI) return;
    int b = gid / DI, d = gid % DI;

    float An = -__expf(A_log[d * DS + n]);
    float Dd = Dskip[d];

    const float* dtp = dt  + (long)b * Lv * DI + d;
    const float* xcp = xc  + (long)b * Lv * DI + d;
    const float* dbp = dbc + (long)b * Lv * XPN;
    const float* zp  = xz  + (long)b * Lv * (2 * DI) + DI + d;
    float* yp        = ys  + (long)b * Lv * DI + d;

    float h = 0.f;
    float dtv = dtp[0], xcv = xcp[0];
    float Bn = dbp[DTR + n], Cn = dbp[DTR + DS + n];
    float zv = zp[0];

    for (int l = 0; l < Lv; l++) {
        float dt2 = 0.f, xc2 = 0.f, B2 = 0.f, C2 = 0.f, z2 = 0.f;
        if (l + 1 < Lv) {
            dt2 = dtp[(l + 1) * DI];
            xc2 = xcp[(l + 1) * DI];
            B2  = dbp[(l + 1) * XPN + DTR + n];
            C2  = dbp[(l + 1) * XPN + DTR + DS + n];
            z2  = zp[(l + 1) * 2 * DI];
        }
        float dA = __expf(dtv * An);
        h = fmaf(dA, h, dtv * xcv * Bn);
        float p = h * Cn;
        p += __shfl_xor_sync(0xffffffffu, p, 8);
        p += __shfl_xor_sync(0xffffffffu, p, 4);
        p += __shfl_xor_sync(0xffffffffu, p, 2);
        p += __shfl_xor_sync(0xffffffffu, p, 1);
        if (n == 0) {
            float y = p + xcv * Dd;
            y *= silu_f(zv);
            yp[l * DI] = y;
        }
        dtv = dt2; xcv = xc2; Bn = B2; Cn = C2; zv = z2;
    }
}

// ---------------- launch ----------------
extern "C" void kernel_launch(void* const* d_in, const int* in_sizes, int n_in,
                              void* d_out, int out_size)
{
    const float* hidden = (const float*)d_in[0];
    float* out = (float*)d_out;

    float *xz, *xc, *dbc, *dtb_buf, *ys, *od;
    cudaGetSymbolAddress((void**)&xz,      g_xz);
    cudaGetSymbolAddress((void**)&xc,      g_xc);
    cudaGetSymbolAddress((void**)&dbc,     g_dbc);
    cudaGetSymbolAddress((void**)&dtb_buf, g_dt);
    cudaGetSymbolAddress((void**)&ys,      g_ys);
    cudaGetSymbolAddress((void**)&od,      g_od);

    const dim3 blk(256);

    for (int dir = 0; dir < 2; dir++) {
        const int o = 1 + 9 * dir;
        const float* in_w    = (const float*)d_in[o + 0];
        const float* conv_w  = (const float*)d_in[o + 1];
        const float* conv_b  = (const float*)d_in[o + 2];
        const float* xproj_w = (const float*)d_in[o + 3];
        const float* dt_w    = (const float*)d_in[o + 4];
        const float* dt_b    = (const float*)d_in[o + 5];
        const float* A_log   = (const float*)d_in[o + 6];
        const float* D_skip  = (const float*)d_in[o + 7];
        const float* out_w   = (const float*)d_in[o + 8];

        // 1. in_proj: (4096,512)@(512,2048) -> xz  (bwd reads rows reversed)
        gemmT<128, 8, 0><<<dim3(2048 / 128, ROWS / 128), blk>>>(
            hidden, in_w, nullptr, xz, 2 * DI, DM, DM, 2 * DI, dir, 0);

        // 2. conv + silu -> xc
        conv_silu_kernel<<<(ROWS * DI) / 256, blk>>>(xz, conv_w, conv_b, xc);

        // 3. xproj: (4096,1024)@(1024,64) -> dbc
        gemmT<64, 4, 0><<<dim3(XPN / 64, ROWS / 128), blk>>>(
            xc, xproj_w, nullptr, dbc, XPN, DI, DI, XPN, 0, 0);

        // 4. dt proj + softplus: (4096,32)@(32,1024) -> dt   (A = dbc[:, :32], lda=64)
        gemmT<128, 8, 1><<<dim3(DI / 128, ROWS / 128), blk>>>(
            dbc, dt_w, dt_b, dtb_buf, DI, DTR, XPN, DI, 0, 0);

        // 5. selective scan -> ys
        scan_kernel<<<(Bv * DI * 16) / 256, blk>>>(
            dtb_buf, xc, dbc, xz, A_log, D_skip, ys);

        // 6. out_proj: (4096,1024)@(1024,512) -> od[:, dir*512:dir*512+512]
        //    (bwd writes rows reversed)
        gemmT<128, 8, 0><<<dim3(DM / 128, ROWS / 128), blk>>>(
            ys, out_w, nullptr, od + dir * DM, DM, DI, DI, 2 * DM, 0, dir);
    }

    const float* fuse_w = (const float*)d_in[19];
    const float* fuse_b = (const float*)d_in[20];

    // fuse: (4096,1024)@(1024,512)+bias -> out   (single GEMM, od interleaved)
    gemmT<128, 8, 0><<<dim3(DM / 128, ROWS / 128), blk>>>(
        od, fuse_w, fuse_b, out, DM, 2 * DM, 2 * DM, DM, 0, 0);
}

// round 3
// speedup vs baseline: 2.0391x; 1.7847x over previous
#include <cuda_runtime.h>
#include <math.h>

#define Bv   2
#define Lv   2048
#define DM   512
#define DI   1024
#define DS   16
#define DTR  32
#define ROWS (Bv * Lv)      // 4096
#define XPN  (DTR + 2*DS)   // 64
#define NC   32             // chunks per sequence
#define CL   (Lv / NC)      // 64 steps per chunk

// ---------------- scratch (dir-indexed) ----------------
__device__ float g_xz [2][ROWS * 2 * DI];
__device__ float g_xc [2][ROWS * DI];
__device__ float g_dbc[2][ROWS * XPN];
__device__ float g_dt [2][ROWS * DI];
__device__ float g_ys [2][ROWS * DI];
__device__ float g_od [ROWS * 2 * DM];           // interleaved [row][dir*512+col]
__device__ float g_sumdt[2 * Bv * NC * DI];      // per-chunk sum(dt)
__device__ float g_S    [2 * Bv * NC * DI * DS]; // per-chunk local final state
__device__ float g_H0   [2 * Bv * NC * DI * DS]; // per-chunk initial state

__device__ __forceinline__ float silu_f(float x) { return x / (1.f + __expf(-x)); }

// ================= 128xBN double-buffered fp32 GEMM, dir-batched =================
template<int BN, int TN, int SOFTPLUS>
__global__ __launch_bounds__(256, 2)
void gemmT(const float* __restrict__ A0, const float* __restrict__ A1,
           const float* __restrict__ W0, const float* __restrict__ W1,
           const float* __restrict__ b0, const float* __restrict__ b1,
           float* __restrict__ C0, float* __restrict__ C1,
           int N, int K, int lda, int ldc, int revAmask, int revCmask)
{
    constexpr int BM = 128;
    __shared__ float As[2][16][BM + 4];
    __shared__ float Ws[2][16][BN + 4];

    const int dir = blockIdx.z;
    const float* A = dir ? A1 : A0;
    const float* W = dir ? W1 : W0;
    const float* bias = dir ? b1 : b0;
    float* C = dir ? C1 : C0;
    const int revA = (revAmask >> dir) & 1;
    const int revC = (revCmask >> dir) & 1;

    const int tid = threadIdx.x;
    const int tx = tid & 15, ty = tid >> 4;
    const long m0 = (long)blockIdx.y * BM;
    const int n0 = blockIdx.x * BN;

    const int ar  = tid >> 2;
    const int akq = (tid & 3) * 4;
    long arow0 = m0 + ar, arow1 = m0 + ar + 64;
    if (revA) {
        long bb = arow0 >> 11, l0 = arow0 & 2047; arow0 = (bb << 11) + (2047 - l0);
        long b1r = arow1 >> 11, l1 = arow1 & 2047; arow1 = (b1r << 11) + (2047 - l1);
    }
    const float* Ap0 = A + arow0 * lda + akq;
    const float* Ap1 = A + arow1 * lda + akq;

    int wk0, wc0, wk1 = 0;
    const float *Wp0, *Wp1 = nullptr;
    if (BN == 128) {
        wk0 = tid >> 5; wc0 = (tid & 31) * 4; wk1 = wk0 + 8;
        Wp0 = W + (long)wk0 * N + n0 + wc0;
        Wp1 = W + (long)wk1 * N + n0 + wc0;
    } else {
        wk0 = tid >> 4; wc0 = (tid & 15) * 4;
        Wp0 = W + (long)wk0 * N + n0 + wc0;
    }

    float acc[8][TN];
#pragma unroll
    for (int i = 0; i < 8; i++)
#pragma unroll
        for (int j = 0; j < TN; j++) acc[i][j] = 0.f;

    const int nb = K >> 4;

    float4 pa0 = *(const float4*)Ap0;
    float4 pa1 = *(const float4*)Ap1;
    float4 pw0 = *(const float4*)Wp0;
    float4 pw1 = (BN == 128) ? *(const float4*)Wp1 : make_float4(0,0,0,0);

    As[0][akq + 0][ar] = pa0.x; As[0][akq + 1][ar] = pa0.y;
    As[0][akq + 2][ar] = pa0.z; As[0][akq + 3][ar] = pa0.w;
    As[0][akq + 0][ar + 64] = pa1.x; As[0][akq + 1][ar + 64] = pa1.y;
    As[0][akq + 2][ar + 64] = pa1.z; As[0][akq + 3][ar + 64] = pa1.w;
    *(float4*)&Ws[0][wk0][wc0] = pw0;
    if (BN == 128) *(float4*)&Ws[0][wk1][wc0] = pw1;
    __syncthreads();

    for (int kb = 0; kb < nb; kb++) {
        const int cur = kb & 1;
        if (kb + 1 < nb) {
            const int ko = (kb + 1) * 16;
            pa0 = *(const float4*)(Ap0 + ko);
            pa1 = *(const float4*)(Ap1 + ko);
            pw0 = *(const float4*)(Wp0 + (long)ko * N);
            if (BN == 128) pw1 = *(const float4*)(Wp1 + (long)ko * N);
        }
#pragma unroll
        for (int kk = 0; kk < 16; kk++) {
            float4 a0 = *(const float4*)&As[cur][kk][ty * 4];
            float4 a1 = *(const float4*)&As[cur][kk][64 + ty * 4];
            float4 bq0 = *(const float4*)&Ws[cur][kk][tx * 4];
            float av[8] = {a0.x, a0.y, a0.z, a0.w, a1.x, a1.y, a1.z, a1.w};
            float bvv[TN];
            bvv[0] = bq0.x; bvv[1] = bq0.y; bvv[2] = bq0.z; bvv[3] = bq0.w;
            if (TN == 8) {
                float4 bq1 = *(const float4*)&Ws[cur][kk][64 + tx * 4];
                bvv[4] = bq1.x; bvv[5] = bq1.y; bvv[6] = bq1.z; bvv[7] = bq1.w;
            }
#pragma unroll
            for (int i = 0; i < 8; i++)
#pragma unroll
                for (int j = 0; j < TN; j++)
                    acc[i][j] = fmaf(av[i], bvv[j], acc[i][j]);
        }
        if (kb + 1 < nb) {
            const int nxt = cur ^ 1;
            As[nxt][akq + 0][ar] = pa0.x; As[nxt][akq + 1][ar] = pa0.y;
            As[nxt][akq + 2][ar] = pa0.z; As[nxt][akq + 3][ar] = pa0.w;
            As[nxt][akq + 0][ar + 64] = pa1.x; As[nxt][akq + 1][ar + 64] = pa1.y;
            As[nxt][akq + 2][ar + 64] = pa1.z; As[nxt][akq + 3][ar + 64] = pa1.w;
            *(float4*)&Ws[nxt][wk0][wc0] = pw0;
            if (BN == 128) *(float4*)&Ws[nxt][wk1][wc0] = pw1;
            __syncthreads();
        }
    }

#pragma unroll
    for (int c = 0; c < 2; c++) {
#pragma unroll
        for (int i = 0; i < 4; i++) {
            long row = m0 + c * 64 + ty * 4 + i;
            long grow = row;
            if (revC) { long bb = row >> 11, l = row & 2047; grow = (bb << 11) + (2047 - l); }
            float* Crow = C + grow * ldc + n0;
#pragma unroll
            for (int jc = 0; jc < TN / 4; jc++) {
                float4 v;
                float* a = &acc[c * 4 + i][jc * 4];
                v.x = a[0]; v.y = a[1]; v.z = a[2]; v.w = a[3];
                if (bias) {
                    const float* bp = bias + n0 + jc * 64 + tx * 4;
                    v.x += bp[0]; v.y += bp[1]; v.z += bp[2]; v.w += bp[3];
                }
                if (SOFTPLUS) {
                    v.x = (v.x > 20.f) ? v.x : log1pf(__expf(v.x));
                    v.y = (v.y > 20.f) ? v.y : log1pf(__expf(v.y));
                    v.z = (v.z > 20.f) ? v.z : log1pf(__expf(v.z));
                    v.w = (v.w > 20.f) ? v.w : log1pf(__expf(v.w));
                }
                *(float4*)(Crow + jc * 64 + tx * 4) = v;
            }
        }
    }
}

// ---------------- depthwise causal conv + SiLU (both dirs) ----------------
__global__ void conv_silu_kernel(const float* __restrict__ cw0, const float* __restrict__ cb0,
                                 const float* __restrict__ cw1, const float* __restrict__ cb1)
{
    int idx = blockIdx.x * blockDim.x + threadIdx.x;
    int dir = idx >= ROWS * DI;
    int rem = idx - dir * ROWS * DI;
    const float* cw = dir ? cw1 : cw0;
    const float* cb = dir ? cb1 : cb0;
    const float* xz = g_xz[dir];
    float* xc = g_xc[dir];

    int d   = rem & (DI - 1);
    int row = rem >> 10;
    int l   = row & (Lv - 1);
    float s = cb[d];
    float w0 = cw[d * 4 + 0], w1 = cw[d * 4 + 1],
          w2 = cw[d * 4 + 2], w3 = cw[d * 4 + 3];
    const float* xp = xz + (long)row * (2 * DI) + d;
    if (l >= 3) s = fmaf(w0, xp[-3 * 2 * DI], s);
    if (l >= 2) s = fmaf(w1, xp[-2 * 2 * DI], s);
    if (l >= 1) s = fmaf(w2, xp[-1 * 2 * DI], s);
    s = fmaf(w3, xp[0], s);
    xc[rem] = silu_f(s);
}

// ---------------- scan pass 1: local chunk scans (h0 = 0) ----------------
// group g = ((dir*Bv + b)*NC + c)*DI + d ; 16 lanes = 16 states
__global__ void scan_p1(const float* __restrict__ A_log0, const float* __restrict__ A_log1)
{
    int t = blockIdx.x * blockDim.x + threadIdx.x;
    int n = t & 15;
    int g = t >> 4;
    int d = g & (DI - 1);
    int g2 = g >> 10;
    int c = g2 & (NC - 1);
    int g3 = g2 >> 5;
    int b = g3 & 1;
    int dir = g3 >> 1;

    const float* A_log = dir ? A_log1 : A_log0;
    float An = -__expf(A_log[d * DS + n]);

    const float* dtp = g_dt[dir]  + ((long)b * Lv + c * CL) * DI + d;
    const float* xcp = g_xc[dir]  + ((long)b * Lv + c * CL) * DI + d;
    const float* dbp = g_dbc[dir] + ((long)b * Lv + c * CL) * XPN;

    float h = 0.f, sdt = 0.f;
#pragma unroll 4
    for (int l = 0; l < CL; l++) {
        float dtv = dtp[l * DI];
        float xcv = xcp[l * DI];
        float Bn  = dbp[l * XPN + DTR + n];
        float dA = __expf(dtv * An);
        h = fmaf(dA, h, dtv * xcv * Bn);
        sdt += dtv;
    }
    g_S[(long)g * DS + n] = h;
    if (n == 0) g_sumdt[g] = sdt;
}

// ---------------- scan pass 2: scan chunk summaries ----------------
// thread per (dir,b,d,n); loops NC chunks sequentially
__global__ void scan_p2(const float* __restrict__ A_log0, const float* __restrict__ A_log1)
{
    int t = blockIdx.x * blockDim.x + threadIdx.x;
    int n = t & 15;
    int g = t >> 4;
    int d = g & (DI - 1);
    int g2 = g >> 10;
    int b = g2 & 1;
    int dir = g2 >> 1;

    const float* A_log = dir ? A_log1 : A_log0;
    float An = -__expf(A_log[d * DS + n]);

    long base = (((long)(dir * Bv + b)) * NC) * DI + d;   // + c*DI per chunk
    float h = 0.f;
    for (int c = 0; c < NC; c++) {
        long idx = base + (long)c * DI;
        g_H0[idx * DS + n] = h;
        float P = __expf(An * g_sumdt[idx]);
        h = fmaf(P, h, g_S[idx * DS + n]);
    }
}

// ---------------- scan pass 3: re-run chunks with real h0, emit y ----------------
__global__ void scan_p3(const float* __restrict__ A_log0, const float* __restrict__ A_log1,
                        const float* __restrict__ Dsk0,   const float* __restrict__ Dsk1)
{
    int t = blockIdx.x * blockDim.x + threadIdx.x;
    int n = t & 15;
    int g = t >> 4;
    int d = g & (DI - 1);
    int g2 = g >> 10;
    int c = g2 & (NC - 1);
    int g3 = g2 >> 5;
    int b = g3 & 1;
    int dir = g3 >> 1;

    const float* A_log = dir ? A_log1 : A_log0;
    const float* Dsk   = dir ? Dsk1 : Dsk0;
    float An = -__expf(A_log[d * DS + n]);
    float Dd = Dsk[d];

    const float* dtp = g_dt[dir]  + ((long)b * Lv + c * CL) * DI + d;
    const float* xcp = g_xc[dir]  + ((long)b * Lv + c * CL) * DI + d;
    const float* dbp = g_dbc[dir] + ((long)b * Lv + c * CL) * XPN;
    const float* zp  = g_xz[dir]  + ((long)b * Lv + c * CL) * (2 * DI) + DI + d;
    float* yp        = g_ys[dir]  + ((long)b * Lv + c * CL) * DI + d;

    float h = g_H0[(long)g * DS + n];

    for (int l = 0; l < CL; l++) {
        float dtv = dtp[l * DI];
        float xcv = xcp[l * DI];
        float Bn  = dbp[l * XPN + DTR + n];
        float Cn  = dbp[l * XPN + DTR + DS + n];
        float dA = __expf(dtv * An);
        h = fmaf(dA, h, dtv * xcv * Bn);
        float p = h * Cn;
        p += __shfl_xor_sync(0xffffffffu, p, 8);
        p += __shfl_xor_sync(0xffffffffu, p, 4);
        p += __shfl_xor_sync(0xffffffffu, p, 2);
        p += __shfl_xor_sync(0xffffffffu, p, 1);
        if (n == 0) {
            float zv = zp[l * 2 * DI];
            float y = p + xcv * Dd;
            yp[l * DI] = y * silu_f(zv);
        }
    }
}

// ---------------- launch ----------------
extern "C" void kernel_launch(void* const* d_in, const int* in_sizes, int n_in,
                              void* d_out, int out_size)
{
    const float* hidden = (const float*)d_in[0];
    float* out = (float*)d_out;

    float *xz, *xc, *dbc, *dtb, *ys, *od;
    cudaGetSymbolAddress((void**)&xz,  g_xz);
    cudaGetSymbolAddress((void**)&xc,  g_xc);
    cudaGetSymbolAddress((void**)&dbc, g_dbc);
    cudaGetSymbolAddress((void**)&dtb, g_dt);
    cudaGetSymbolAddress((void**)&ys,  g_ys);
    cudaGetSymbolAddress((void**)&od,  g_od);

    const float* p[2][9];
    for (int dir = 0; dir < 2; dir++)
        for (int k = 0; k < 9; k++)
            p[dir][k] = (const float*)d_in[1 + 9 * dir + k];
    // k: 0 in_w, 1 conv_w, 2 conv_b, 3 xproj_w, 4 dt_w, 5 dt_b, 6 A_log, 7 D_skip, 8 out_w

    const long SXZ = (long)ROWS * 2 * DI, SXC = (long)ROWS * DI;
    const long SDB = (long)ROWS * XPN;
    const dim3 blk(256);

    // 1. in_proj (both dirs): bwd reads rows reversed
    gemmT<128, 8, 0><<<dim3(16, 32, 2), blk>>>(
        hidden, hidden, p[0][0], p[1][0], nullptr, nullptr,
        xz, xz + SXZ, 2 * DI, DM, DM, 2 * DI, 0b10, 0);

    // 2. conv + silu (both dirs)
    conv_silu_kernel<<<(2 * ROWS * DI) / 256, blk>>>(p[0][1], p[0][2], p[1][1], p[1][2]);

    // 3. xproj (both dirs)
    gemmT<64, 4, 0><<<dim3(1, 32, 2), blk>>>(
        xc, xc + SXC, p[0][3], p[1][3], nullptr, nullptr,
        dbc, dbc + SDB, XPN, DI, DI, XPN, 0, 0);

    // 4. dt proj + softplus (both dirs): A = dbc[:, :32] with lda=64
    gemmT<128, 8, 1><<<dim3(8, 32, 2), blk>>>(
        dbc, dbc + SDB, p[0][4], p[1][4], p[0][5], p[1][5],
        dtb, dtb + SXC, DI, DTR, XPN, DI, 0, 0);

    // 5. chunked parallel scan
    scan_p1<<<(2 * Bv * NC * DI * 16) / 256, blk>>>(p[0][6], p[1][6]);
    scan_p2<<<(2 * Bv * DI * 16) / 256, blk>>>(p[0][6], p[1][6]);
    scan_p3<<<(2 * Bv * NC * DI * 16) / 256, blk>>>(p[0][6], p[1][6], p[0][7], p[1][7]);

    // 6. out_proj (both dirs) -> od interleaved; bwd writes rows reversed
    gemmT<128, 8, 0><<<dim3(4, 32, 2), blk>>>(
        ys, ys + SXC, p[0][8], p[1][8], nullptr, nullptr,
        od, od + DM, DM, DI, DI, 2 * DM, 0, 0b10);

    const float* fuse_w = (const float*)d_in[19];
    const float* fuse_b = (const float*)d_in[20];

    // 7. fuse: (4096,1024)@(1024,512)+bias -> out
    gemmT<128, 8, 0><<<dim3(4, 32, 1), blk>>>(
        od, od, fuse_w, fuse_w, fuse_b, fuse_b,
        out, out, DM, 2 * DM, 2 * DM, DM, 0, 0);
}

// round 5
// speedup vs baseline: 3.0137x; 1.4780x over previous
#include <cuda_runtime.h>
#include <cstdint>
#include <math.h>

#define Bv   2
#define Lv   2048
#define DM   512
#define DI   1024
#define DS   16
#define DTR  32
#define ROWS (Bv * Lv)      // 4096
#define XPN  (DTR + 2*DS)   // 64
#define NC   32
#define CL   (Lv / NC)      // 64

// ---------------- scratch ----------------
__device__ float g_xz [2][ROWS * 2 * DI];
__device__ float g_xc [2][ROWS * DI];
__device__ float g_dbc[2][ROWS * XPN];
__device__ float g_dt [2][ROWS * DI];
__device__ float g_ys [2][ROWS * DI];
__device__ float g_od [ROWS * 2 * DM];
__device__ float g_sumdt[2 * Bv * NC * DI];
__device__ float g_S    [2 * Bv * NC * DI * DS];
__device__ float g_H0   [2 * Bv * NC * DI * DS];
// transposed (tf32-rounded) weights, layout [N,K]
#define WT_IN(dir)    ((long)(dir) * 1048576)
#define WT_XP(dir)    (2097152 + (long)(dir) * 65536)
#define WT_DT(dir)    (2228224 + (long)(dir) * 32768)
#define WT_OUT(dir)   (2293760 + (long)(dir) * 524288)
#define WT_FUSE       (3342336)
__device__ float g_wT[3866624];

__device__ __forceinline__ float silu_f(float x) { return x / (1.f + __expf(-x)); }
__device__ __forceinline__ float tf32r(float x) {
    float r; asm("cvt.rna.tf32.f32 %0, %1;" : "=f"(r) : "f"(x)); return r;
}

// warp-level tf32 MMA (family-portable PTX, sm_80+)
__device__ __forceinline__ void mma8(float d[4], const float a[4], const float b[2]) {
    asm volatile("mma.sync.aligned.m16n8k8.row.col.f32.tf32.tf32.f32 "
        "{%0,%1,%2,%3}, {%4,%5,%6,%7}, {%8,%9}, {%0,%1,%2,%3};"
        : "+f"(d[0]), "+f"(d[1]), "+f"(d[2]), "+f"(d[3])
        : "r"(__float_as_uint(a[0])), "r"(__float_as_uint(a[1])),
          "r"(__float_as_uint(a[2])), "r"(__float_as_uint(a[3])),
          "r"(__float_as_uint(b[0])), "r"(__float_as_uint(b[1])));
}

// ---------------- weight transpose + tf32 round: out[n*K+k] = in[k*N+n] ----------------
__global__ void transpose_cvt(const float* __restrict__ in, float* __restrict__ outp,
                              int K, int N)
{
    __shared__ float t[32][33];
    int k0 = blockIdx.x * 32, n0 = blockIdx.y * 32;
    int x = threadIdx.x, y = threadIdx.y;
#pragma unroll
    for (int i = 0; i < 32; i += 8)
        t[y + i][x] = in[(long)(k0 + y + i) * N + n0 + x];
    __syncthreads();
#pragma unroll
    for (int i = 0; i < 32; i += 8)
        outp[(long)(n0 + y + i) * K + k0 + x] = tf32r(t[x][y + i]);
}

// ================= tf32 mma.sync GEMM: C[M,N] = A[M,K] @ Wt[N,K]^T =================
// 256 threads = 8 warps (4 M x 2 N). Tile 128 x NT. K staged 16, double buffered.
template<int NT, int SOFTPLUS>
__global__ __launch_bounds__(256, 2)
void gemm_mma(const float* __restrict__ A0, const float* __restrict__ A1,
              const float* __restrict__ W0, const float* __restrict__ W1,
              const float* __restrict__ b0, const float* __restrict__ b1,
              float* __restrict__ C0, float* __restrict__ C1,
              int K, int lda, int ldc, int revAmask, int revCmask)
{
    constexpr int WN = NT / 2;      // cols per N-warp
    constexpr int NTILES = WN / 8;  // n8 tiles per warp
    constexpr int BJ = NT / 64;     // B float4 loads per thread
    __shared__ float As[2][128][20];
    __shared__ float Ws[2][NT][20];

    const int tid = threadIdx.x;
    const int wid = tid >> 5, lane = tid & 31;
    const int wm = wid & 3, wn = wid >> 2;
    const int g = lane >> 2, t = lane & 3;

    const int dir = blockIdx.z;
    const float* A = dir ? A1 : A0;
    const float* W = dir ? W1 : W0;
    const float* bias = dir ? b1 : b0;
    float* C = dir ? C1 : C0;
    const int revA = (revAmask >> dir) & 1, revC = (revCmask >> dir) & 1;
    const long m0 = (long)blockIdx.y * 128;
    const int n0 = blockIdx.x * NT;

    // ---- loaders: A 512 quads (2/thread), B NT*4 quads (BJ/thread) ----
    const float* aptr[2]; int asr[2], asq[2];
#pragma unroll
    for (int j = 0; j < 2; j++) {
        int qi = tid + j * 256;
        int row = qi >> 2, q = qi & 3;
        long arow = m0 + row;
        if (revA) { long bb = arow >> 11, l = arow & 2047; arow = (bb << 11) + (2047 - l); }
        aptr[j] = A + arow * lda + q * 4;
        asr[j] = row; asq[j] = q;
    }
    const float* bptr[BJ]; int bsr[BJ], bsq[BJ];
#pragma unroll
    for (int j = 0; j < BJ; j++) {
        int qi = tid + j * 256;
        int row = qi >> 2, q = qi & 3;
        bptr[j] = W + (long)(n0 + row) * K + q * 4;
        bsr[j] = row; bsq[j] = q;
    }

    float acc[2][NTILES][4];
#pragma unroll
    for (int i = 0; i < 2; i++)
#pragma unroll
        for (int j = 0; j < NTILES; j++)
#pragma unroll
            for (int e = 0; e < 4; e++) acc[i][j][e] = 0.f;

    const int nb = K >> 4;
    float4 ra[2], rb[BJ];

    // stage 0
#pragma unroll
    for (int j = 0; j < 2; j++) ra[j] = *(const float4*)(aptr[j]);
#pragma unroll
    for (int j = 0; j < BJ; j++) rb[j] = *(const float4*)(bptr[j]);
#pragma unroll
    for (int j = 0; j < 2; j++) {
        float4 v = ra[j];
        v.x = tf32r(v.x); v.y = tf32r(v.y); v.z = tf32r(v.z); v.w = tf32r(v.w);
        *(float4*)&As[0][asr[j]][asq[j] * 4] = v;
    }
#pragma unroll
    for (int j = 0; j < BJ; j++)
        *(float4*)&Ws[0][bsr[j]][bsq[j] * 4] = rb[j];
    __syncthreads();

    for (int s = 0; s < nb; s++) {
        const int buf = s & 1;
        const bool more = (s + 1 < nb);
        if (more) {
            const int ko = (s + 1) * 16;
#pragma unroll
            for (int j = 0; j < 2; j++) ra[j] = *(const float4*)(aptr[j] + ko);
#pragma unroll
            for (int j = 0; j < BJ; j++) rb[j] = *(const float4*)(bptr[j] + ko);
        }
#pragma unroll
        for (int kk = 0; kk < 2; kk++) {
            float afr[2][4];
#pragma unroll
            for (int mt = 0; mt < 2; mt++) {
                int r = wm * 32 + mt * 16;
                afr[mt][0] = As[buf][r + g     ][kk * 8 + t];
                afr[mt][1] = As[buf][r + g + 8 ][kk * 8 + t];
                afr[mt][2] = As[buf][r + g     ][kk * 8 + t + 4];
                afr[mt][3] = As[buf][r + g + 8 ][kk * 8 + t + 4];
            }
#pragma unroll
            for (int nt = 0; nt < NTILES; nt++) {
                int nc = wn * WN + nt * 8;
                float bfr[2];
                bfr[0] = Ws[buf][nc + g][kk * 8 + t];
                bfr[1] = Ws[buf][nc + g][kk * 8 + t + 4];
                mma8(acc[0][nt], afr[0], bfr);
                mma8(acc[1][nt], afr[1], bfr);
            }
        }
        if (more) {
            const int nbuf = buf ^ 1;
#pragma unroll
            for (int j = 0; j < 2; j++) {
                float4 v = ra[j];
                v.x = tf32r(v.x); v.y = tf32r(v.y); v.z = tf32r(v.z); v.w = tf32r(v.w);
                *(float4*)&As[nbuf][asr[j]][asq[j] * 4] = v;
            }
#pragma unroll
            for (int j = 0; j < BJ; j++)
                *(float4*)&Ws[nbuf][bsr[j]][bsq[j] * 4] = rb[j];
            __syncthreads();
        }
    }

    // ---- epilogue ----
#pragma unroll
    for (int mt = 0; mt < 2; mt++) {
#pragma unroll
        for (int half = 0; half < 2; half++) {
            long row = m0 + wm * 32 + mt * 16 + g + half * 8;
            long grow = row;
            if (revC) { long bb = row >> 11, l = row & 2047; grow = (bb << 11) + (2047 - l); }
            float* Cp = C + grow * ldc + n0 + wn * WN;
#pragma unroll
            for (int nt = 0; nt < NTILES; nt++) {
                int col = nt * 8 + 2 * t;
                float2 v;
                v.x = acc[mt][nt][half * 2 + 0];
                v.y = acc[mt][nt][half * 2 + 1];
                if (bias) {
                    v.x += bias[n0 + wn * WN + col];
                    v.y += bias[n0 + wn * WN + col + 1];
                }
                if (SOFTPLUS) {
                    v.x = (v.x > 20.f) ? v.x : log1pf(__expf(v.x));
                    v.y = (v.y > 20.f) ? v.y : log1pf(__expf(v.y));
                }
                *(float2*)(Cp + col) = v;
            }
        }
    }
}

// ---------------- depthwise causal conv + SiLU ----------------
__global__ void conv_silu_kernel(const float* __restrict__ cw0, const float* __restrict__ cb0,
                                 const float* __restrict__ cw1, const float* __restrict__ cb1)
{
    int idx = blockIdx.x * blockDim.x + threadIdx.x;
    int dir = idx >= ROWS * DI;
    int rem = idx - dir * ROWS * DI;
    const float* cw = dir ? cw1 : cw0;
    const float* cb = dir ? cb1 : cb0;
    const float* xz = g_xz[dir];
    float* xc = g_xc[dir];

    int d   = rem & (DI - 1);
    int row = rem >> 10;
    int l   = row & (Lv - 1);
    float s = cb[d];
    float w0 = cw[d * 4 + 0], w1 = cw[d * 4 + 1],
          w2 = cw[d * 4 + 2], w3 = cw[d * 4 + 3];
    const float* xp = xz + (long)row * (2 * DI) + d;
    if (l >= 3) s = fmaf(w0, xp[-3 * 2 * DI], s);
    if (l >= 2) s = fmaf(w1, xp[-2 * 2 * DI], s);
    if (l >= 1) s = fmaf(w2, xp[-1 * 2 * DI], s);
    s = fmaf(w3, xp[0], s);
    xc[rem] = silu_f(s);
}

// ---------------- scan pass 1 ----------------
__global__ void scan_p1(const float* __restrict__ A_log0, const float* __restrict__ A_log1)
{
    int t = blockIdx.x * blockDim.x + threadIdx.x;
    int n = t & 15;
    int g = t >> 4;
    int d = g & (DI - 1);
    int g2 = g >> 10;
    int c = g2 & (NC - 1);
    int g3 = g2 >> 5;
    int b = g3 & 1;
    int dir = g3 >> 1;

    const float* A_log = dir ? A_log1 : A_log0;
    float An = -__expf(A_log[d * DS + n]);

    const float* dtp = g_dt[dir]  + ((long)b * Lv + c * CL) * DI + d;
    const float* xcp = g_xc[dir]  + ((long)b * Lv + c * CL) * DI + d;
    const float* dbp = g_dbc[dir] + ((long)b * Lv + c * CL) * XPN;

    float h = 0.f, sdt = 0.f;
#pragma unroll 4
    for (int l = 0; l < CL; l++) {
        float dtv = dtp[l * DI];
        float xcv = xcp[l * DI];
        float Bn  = dbp[l * XPN + DTR + n];
        float dA = __expf(dtv * An);
        h = fmaf(dA, h, dtv * xcv * Bn);
        sdt += dtv;
    }
    g_S[(long)g * DS + n] = h;
    if (n == 0) g_sumdt[g] = sdt;
}

// ---------------- scan pass 2 ----------------
__global__ void scan_p2(const float* __restrict__ A_log0, const float* __restrict__ A_log1)
{
    int t = blockIdx.x * blockDim.x + threadIdx.x;
    int n = t & 15;
    int g = t >> 4;
    int d = g & (DI - 1);
    int g2 = g >> 10;
    int b = g2 & 1;
    int dir = g2 >> 1;

    const float* A_log = dir ? A_log1 : A_log0;
    float An = -__expf(A_log[d * DS + n]);

    long base = (((long)(dir * Bv + b)) * NC) * DI + d;
    float h = 0.f;
    for (int c = 0; c < NC; c++) {
        long idx = base + (long)c * DI;
        g_H0[idx * DS + n] = h;
        float P = __expf(An * g_sumdt[idx]);
        h = fmaf(P, h, g_S[idx * DS + n]);
    }
}

// ---------------- scan pass 3 ----------------
__global__ void scan_p3(const float* __restrict__ A_log0, const float* __restrict__ A_log1,
                        const float* __restrict__ Dsk0,   const float* __restrict__ Dsk1)
{
    int t = blockIdx.x * blockDim.x + threadIdx.x;
    int n = t & 15;
    int g = t >> 4;
    int d = g & (DI - 1);
    int g2 = g >> 10;
    int c = g2 & (NC - 1);
    int g3 = g2 >> 5;
    int b = g3 & 1;
    int dir = g3 >> 1;

    const float* A_log = dir ? A_log1 : A_log0;
    const float* Dsk   = dir ? Dsk1 : Dsk0;
    float An = -__expf(A_log[d * DS + n]);
    float Dd = Dsk[d];

    const float* dtp = g_dt[dir]  + ((long)b * Lv + c * CL) * DI + d;
    const float* xcp = g_xc[dir]  + ((long)b * Lv + c * CL) * DI + d;
    const float* dbp = g_dbc[dir] + ((long)b * Lv + c * CL) * XPN;
    const float* zp  = g_xz[dir]  + ((long)b * Lv + c * CL) * (2 * DI) + DI + d;
    float* yp        = g_ys[dir]  + ((long)b * Lv + c * CL) * DI + d;

    float h = g_H0[(long)g * DS + n];

    for (int l = 0; l < CL; l++) {
        float dtv = dtp[l * DI];
        float xcv = xcp[l * DI];
        float Bn  = dbp[l * XPN + DTR + n];
        float Cn  = dbp[l * XPN + DTR + DS + n];
        float dA = __expf(dtv * An);
        h = fmaf(dA, h, dtv * xcv * Bn);
        float p = h * Cn;
        p += __shfl_xor_sync(0xffffffffu, p, 8);
        p += __shfl_xor_sync(0xffffffffu, p, 4);
        p += __shfl_xor_sync(0xffffffffu, p, 2);
        p += __shfl_xor_sync(0xffffffffu, p, 1);
        if (n == 0) {
            float zv = zp[l * 2 * DI];
            float y = p + xcv * Dd;
            yp[l * DI] = y * silu_f(zv);
        }
    }
}

// ---------------- launch ----------------
extern "C" void kernel_launch(void* const* d_in, const int* in_sizes, int n_in,
                              void* d_out, int out_size)
{
    const float* hidden = (const float*)d_in[0];
    float* out = (float*)d_out;

    float *xz, *xc, *dbc, *dtb, *ys, *od, *wT;
    cudaGetSymbolAddress((void**)&xz,  g_xz);
    cudaGetSymbolAddress((void**)&xc,  g_xc);
    cudaGetSymbolAddress((void**)&dbc, g_dbc);
    cudaGetSymbolAddress((void**)&dtb, g_dt);
    cudaGetSymbolAddress((void**)&ys,  g_ys);
    cudaGetSymbolAddress((void**)&od,  g_od);
    cudaGetSymbolAddress((void**)&wT,  g_wT);

    const float* p[2][9];
    for (int dir = 0; dir < 2; dir++)
        for (int k = 0; k < 9; k++)
            p[dir][k] = (const float*)d_in[1 + 9 * dir + k];
    const float* fuse_w = (const float*)d_in[19];
    const float* fuse_b = (const float*)d_in[20];

    const long SXZ = (long)ROWS * 2 * DI, SXC = (long)ROWS * DI;
    const long SDB = (long)ROWS * XPN;

    const dim3 tb(32, 8);
    for (int dir = 0; dir < 2; dir++) {
        transpose_cvt<<<dim3(512 / 32, 2048 / 32), tb>>>(p[dir][0], wT + WT_IN(dir),  512, 2048);
        transpose_cvt<<<dim3(1024 / 32, 64 / 32),  tb>>>(p[dir][3], wT + WT_XP(dir),  1024, 64);
        transpose_cvt<<<dim3(32 / 32, 1024 / 32),  tb>>>(p[dir][4], wT + WT_DT(dir),  32, 1024);
        transpose_cvt<<<dim3(1024 / 32, 512 / 32), tb>>>(p[dir][8], wT + WT_OUT(dir), 1024, 512);
    }
    transpose_cvt<<<dim3(1024 / 32, 512 / 32), tb>>>(fuse_w, wT + WT_FUSE, 1024, 512);

    // 1. in_proj: (4096,512)@Wt[2048,512]^T -> xz  (bwd reads rows reversed)
    gemm_mma<128, 0><<<dim3(16, 32, 2), 256>>>(
        hidden, hidden, wT + WT_IN(0), wT + WT_IN(1), nullptr, nullptr,
        xz, xz + SXZ, DM, DM, 2 * DI, 0b10, 0);

    // 2. conv + silu
    conv_silu_kernel<<<(2 * ROWS * DI) / 256, 256>>>(p[0][1], p[0][2], p[1][1], p[1][2]);

    // 3. xproj: (4096,1024)@Wt[64,1024]^T -> dbc
    gemm_mma<64, 0><<<dim3(1, 32, 2), 256>>>(
        xc, xc + SXC, wT + WT_XP(0), wT + WT_XP(1), nullptr, nullptr,
        dbc, dbc + SDB, DI, DI, XPN, 0, 0);

    // 4. dt proj + softplus: (4096,32 of dbc)@Wt[1024,32]^T -> dt
    gemm_mma<128, 1><<<dim3(8, 32, 2), 256>>>(
        dbc, dbc + SDB, wT + WT_DT(0), wT + WT_DT(1), p[0][5], p[1][5],
        dtb, dtb + SXC, DTR, XPN, DI, 0, 0);

    // 5. chunked parallel scan
    scan_p1<<<(2 * Bv * NC * DI * 16) / 256, 256>>>(p[0][6], p[1][6]);
    scan_p2<<<(2 * Bv * DI * 16) / 256, 256>>>(p[0][6], p[1][6]);
    scan_p3<<<(2 * Bv * NC * DI * 16) / 256, 256>>>(p[0][6], p[1][6], p[0][7], p[1][7]);

    // 6. out_proj -> od interleaved; bwd writes rows reversed
    gemm_mma<128, 0><<<dim3(4, 32, 2), 256>>>(
        ys, ys + SXC, wT + WT_OUT(0), wT + WT_OUT(1), nullptr, nullptr,
        od, od + DM, DI, DI, 2 * DM, 0, 0b10);

    // 7. fuse: (4096,1024)@Wt[512,1024]^T + bias -> out
    gemm_mma<128, 0><<<dim3(4, 32, 1), 256>>>(
        od, od, wT + WT_FUSE, wT + WT_FUSE, fuse_b, fuse_b,
        out, out, 2 * DM, 2 * DM, DM, 0, 0);
}

// round 6
// speedup vs baseline: 4.7776x; 1.5853x over previous
#include <cuda_runtime.h>
#include <cstdint>
#include <math.h>

#define Bv   2
#define Lv   2048
#define DM   512
#define DI   1024
#define DS   16
#define DTR  32
#define ROWS (Bv * Lv)      // 4096
#define XPN  (DTR + 2*DS)   // 64
#define NC   32
#define CL   (Lv / NC)      // 64

// ---------------- scratch ----------------
__device__ float g_xz [2][ROWS * 2 * DI];
__device__ float g_xc [2][ROWS * DI];
__device__ float g_dbc[2][ROWS * XPN];
__device__ float g_dt [2][ROWS * DI];
__device__ float g_ys [2][ROWS * DI];
__device__ float g_od [ROWS * 2 * DM];
__device__ float g_sumdt[2 * Bv * NC * DI];
__device__ float g_S    [2 * Bv * NC * DS * DI];   // [dir][b][c][n][d]
__device__ float g_H0   [2 * Bv * NC * DS * DI];   // [dir][b][c][n][d]
// transposed (tf32-rounded) weights, layout [N,K]
#define WT_IN(dir)    ((long)(dir) * 1048576)
#define WT_XP(dir)    (2097152 + (long)(dir) * 65536)
#define WT_DT(dir)    (2228224 + (long)(dir) * 32768)
#define WT_OUT(dir)   (2293760 + (long)(dir) * 524288)
#define WT_FUSE       (3342336)
__device__ float g_wT[3866624];

__device__ __forceinline__ float silu_f(float x) { return x / (1.f + __expf(-x)); }
__device__ __forceinline__ float tf32r(float x) {
    float r; asm("cvt.rna.tf32.f32 %0, %1;" : "=f"(r) : "f"(x)); return r;
}

// warp-level tf32 MMA (family-portable PTX, sm_80+)
__device__ __forceinline__ void mma8(float d[4], const float a[4], const float b[2]) {
    asm volatile("mma.sync.aligned.m16n8k8.row.col.f32.tf32.tf32.f32 "
        "{%0,%1,%2,%3}, {%4,%5,%6,%7}, {%8,%9}, {%0,%1,%2,%3};"
        : "+f"(d[0]), "+f"(d[1]), "+f"(d[2]), "+f"(d[3])
        : "r"(__float_as_uint(a[0])), "r"(__float_as_uint(a[1])),
          "r"(__float_as_uint(a[2])), "r"(__float_as_uint(a[3])),
          "r"(__float_as_uint(b[0])), "r"(__float_as_uint(b[1])));
}

// ---------------- weight transpose + tf32 round ----------------
__global__ void transpose_cvt(const float* __restrict__ in, float* __restrict__ outp,
                              int K, int N)
{
    __shared__ float t[32][33];
    int k0 = blockIdx.x * 32, n0 = blockIdx.y * 32;
    int x = threadIdx.x, y = threadIdx.y;
#pragma unroll
    for (int i = 0; i < 32; i += 8)
        t[y + i][x] = in[(long)(k0 + y + i) * N + n0 + x];
    __syncthreads();
#pragma unroll
    for (int i = 0; i < 32; i += 8)
        outp[(long)(n0 + y + i) * K + k0 + x] = tf32r(t[x][y + i]);
}

// ================= tf32 mma.sync GEMM: C[M,N] = A[M,K] @ Wt[N,K]^T =================
template<int NT, int SOFTPLUS>
__global__ __launch_bounds__(256, 2)
void gemm_mma(const float* __restrict__ A0, const float* __restrict__ A1,
              const float* __restrict__ W0, const float* __restrict__ W1,
              const float* __restrict__ b0, const float* __restrict__ b1,
              float* __restrict__ C0, float* __restrict__ C1,
              int K, int lda, int ldc, int revAmask, int revCmask)
{
    constexpr int WN = NT / 2;
    constexpr int NTILES = WN / 8;
    constexpr int BJ = NT / 64;
    __shared__ float As[2][128][20];
    __shared__ float Ws[2][NT][20];

    const int tid = threadIdx.x;
    const int wid = tid >> 5, lane = tid & 31;
    const int wm = wid & 3, wn = wid >> 2;
    const int g = lane >> 2, t = lane & 3;

    const int dir = blockIdx.z;
    const float* A = dir ? A1 : A0;
    const float* W = dir ? W1 : W0;
    const float* bias = dir ? b1 : b0;
    float* C = dir ? C1 : C0;
    const int revA = (revAmask >> dir) & 1, revC = (revCmask >> dir) & 1;
    const long m0 = (long)blockIdx.y * 128;
    const int n0 = blockIdx.x * NT;

    const float* aptr[2]; int asr[2], asq[2];
#pragma unroll
    for (int j = 0; j < 2; j++) {
        int qi = tid + j * 256;
        int row = qi >> 2, q = qi & 3;
        long arow = m0 + row;
        if (revA) { long bb = arow >> 11, l = arow & 2047; arow = (bb << 11) + (2047 - l); }
        aptr[j] = A + arow * lda + q * 4;
        asr[j] = row; asq[j] = q;
    }
    const float* bptr[BJ]; int bsr[BJ], bsq[BJ];
#pragma unroll
    for (int j = 0; j < BJ; j++) {
        int qi = tid + j * 256;
        int row = qi >> 2, q = qi & 3;
        bptr[j] = W + (long)(n0 + row) * K + q * 4;
        bsr[j] = row; bsq[j] = q;
    }

    float acc[2][NTILES][4];
#pragma unroll
    for (int i = 0; i < 2; i++)
#pragma unroll
        for (int j = 0; j < NTILES; j++)
#pragma unroll
            for (int e = 0; e < 4; e++) acc[i][j][e] = 0.f;

    const int nb = K >> 4;
    float4 ra[2], rb[BJ];

#pragma unroll
    for (int j = 0; j < 2; j++) ra[j] = *(const float4*)(aptr[j]);
#pragma unroll
    for (int j = 0; j < BJ; j++) rb[j] = *(const float4*)(bptr[j]);
#pragma unroll
    for (int j = 0; j < 2; j++) {
        float4 v = ra[j];
        v.x = tf32r(v.x); v.y = tf32r(v.y); v.z = tf32r(v.z); v.w = tf32r(v.w);
        *(float4*)&As[0][asr[j]][asq[j] * 4] = v;
    }
#pragma unroll
    for (int j = 0; j < BJ; j++)
        *(float4*)&Ws[0][bsr[j]][bsq[j] * 4] = rb[j];
    __syncthreads();

    for (int s = 0; s < nb; s++) {
        const int buf = s & 1;
        const bool more = (s + 1 < nb);
        if (more) {
            const int ko = (s + 1) * 16;
#pragma unroll
            for (int j = 0; j < 2; j++) ra[j] = *(const float4*)(aptr[j] + ko);
#pragma unroll
            for (int j = 0; j < BJ; j++) rb[j] = *(const float4*)(bptr[j] + ko);
        }
#pragma unroll
        for (int kk = 0; kk < 2; kk++) {
            float afr[2][4];
#pragma unroll
            for (int mt = 0; mt < 2; mt++) {
                int r = wm * 32 + mt * 16;
                afr[mt][0] = As[buf][r + g     ][kk * 8 + t];
                afr[mt][1] = As[buf][r + g + 8 ][kk * 8 + t];
                afr[mt][2] = As[buf][r + g     ][kk * 8 + t + 4];
                afr[mt][3] = As[buf][r + g + 8 ][kk * 8 + t + 4];
            }
#pragma unroll
            for (int nt = 0; nt < NTILES; nt++) {
                int nc = wn * WN + nt * 8;
                float bfr[2];
                bfr[0] = Ws[buf][nc + g][kk * 8 + t];
                bfr[1] = Ws[buf][nc + g][kk * 8 + t + 4];
                mma8(acc[0][nt], afr[0], bfr);
                mma8(acc[1][nt], afr[1], bfr);
            }
        }
        if (more) {
            const int nbuf = buf ^ 1;
#pragma unroll
            for (int j = 0; j < 2; j++) {
                float4 v = ra[j];
                v.x = tf32r(v.x); v.y = tf32r(v.y); v.z = tf32r(v.z); v.w = tf32r(v.w);
                *(float4*)&As[nbuf][asr[j]][asq[j] * 4] = v;
            }
#pragma unroll
            for (int j = 0; j < BJ; j++)
                *(float4*)&Ws[nbuf][bsr[j]][bsq[j] * 4] = rb[j];
            __syncthreads();
        }
    }

#pragma unroll
    for (int mt = 0; mt < 2; mt++) {
#pragma unroll
        for (int half = 0; half < 2; half++) {
            long row = m0 + wm * 32 + mt * 16 + g + half * 8;
            long grow = row;
            if (revC) { long bb = row >> 11, l = row & 2047; grow = (bb << 11) + (2047 - l); }
            float* Cp = C + grow * ldc + n0 + wn * WN;
#pragma unroll
            for (int nt = 0; nt < NTILES; nt++) {
                int col = nt * 8 + 2 * t;
                float2 v;
                v.x = acc[mt][nt][half * 2 + 0];
                v.y = acc[mt][nt][half * 2 + 1];
                if (bias) {
                    v.x += bias[n0 + wn * WN + col];
                    v.y += bias[n0 + wn * WN + col + 1];
                }
                if (SOFTPLUS) {
                    v.x = (v.x > 20.f) ? v.x : log1pf(__expf(v.x));
                    v.y = (v.y > 20.f) ? v.y : log1pf(__expf(v.y));
                }
                *(float2*)(Cp + col) = v;
            }
        }
    }
}

// ---------------- depthwise causal conv + SiLU ----------------
__global__ void conv_silu_kernel(const float* __restrict__ cw0, const float* __restrict__ cb0,
                                 const float* __restrict__ cw1, const float* __restrict__ cb1)
{
    int idx = blockIdx.x * blockDim.x + threadIdx.x;
    int dir = idx >= ROWS * DI;
    int rem = idx - dir * ROWS * DI;
    const float* cw = dir ? cw1 : cw0;
    const float* cb = dir ? cb1 : cb0;
    const float* xz = g_xz[dir];
    float* xc = g_xc[dir];

    int d   = rem & (DI - 1);
    int row = rem >> 10;
    int l   = row & (Lv - 1);
    float s = cb[d];
    float w0 = cw[d * 4 + 0], w1 = cw[d * 4 + 1],
          w2 = cw[d * 4 + 2], w3 = cw[d * 4 + 3];
    const float* xp = xz + (long)row * (2 * DI) + d;
    if (l >= 3) s = fmaf(w0, xp[-3 * 2 * DI], s);
    if (l >= 2) s = fmaf(w1, xp[-2 * 2 * DI], s);
    if (l >= 1) s = fmaf(w2, xp[-1 * 2 * DI], s);
    s = fmaf(w3, xp[0], s);
    xc[rem] = silu_f(s);
}

// ================= coalesced chunked scan =================
// thread owns (dir,b,chunk,d) with 16 states in registers.
// block = 256 threads (256 consecutive d); B|C slab for the chunk in smem.

// pass 1: local chunk scan (h0=0) -> g_S [dir][b][c][n][d], g_sumdt
__global__ __launch_bounds__(256)
void scan_p1(const float* __restrict__ A_log0, const float* __restrict__ A_log1)
{
    __shared__ float BC[CL][32];
    const int blk = blockIdx.x;
    const int dq  = blk & 3;
    const int c   = (blk >> 2) & (NC - 1);
    const int b   = (blk >> 7) & 1;
    const int dir = blk >> 8;
    const int d   = dq * 256 + threadIdx.x;

    const float* dbp = g_dbc[dir] + ((long)b * Lv + c * CL) * XPN;
    for (int i = threadIdx.x; i < CL * 32; i += 256)
        BC[i >> 5][i & 31] = dbp[(long)(i >> 5) * XPN + DTR + (i & 31)];
    __syncthreads();

    const float* A_log = dir ? A_log1 : A_log0;
    float An[DS];
#pragma unroll
    for (int n = 0; n < DS; n++) An[n] = -__expf(A_log[d * DS + n]);

    const float* dtp = g_dt[dir] + ((long)b * Lv + c * CL) * DI + d;
    const float* xcp = g_xc[dir] + ((long)b * Lv + c * CL) * DI + d;

    float h[DS];
#pragma unroll
    for (int n = 0; n < DS; n++) h[n] = 0.f;
    float sdt = 0.f;

    for (int l = 0; l < CL; l++) {
        float dt = dtp[l * DI];
        float xc = xcp[l * DI];
        float dx = dt * xc;
        sdt += dt;
#pragma unroll
        for (int n = 0; n < DS; n++)
            h[n] = fmaf(__expf(dt * An[n]), h[n], dx * BC[l][n]);
    }

    long sb = (((long)(dir * Bv + b) * NC + c) * DS) * DI + d;
#pragma unroll
    for (int n = 0; n < DS; n++) g_S[sb + (long)n * DI] = h[n];
    g_sumdt[((long)(dir * Bv + b) * NC + c) * DI + d] = sdt;
}

// pass 2: scan chunk summaries -> g_H0
__global__ __launch_bounds__(256)
void scan_p2(const float* __restrict__ A_log0, const float* __restrict__ A_log1)
{
    int t = blockIdx.x * 256 + threadIdx.x;   // 4096 threads
    int d   = t & (DI - 1);
    int b   = (t >> 10) & 1;
    int dir = t >> 11;

    const float* A_log = dir ? A_log1 : A_log0;
    float An[DS];
#pragma unroll
    for (int n = 0; n < DS; n++) An[n] = -__expf(A_log[d * DS + n]);

    long base_sd = ((long)(dir * Bv + b) * NC) * DI + d;
    long base_S  = ((long)(dir * Bv + b) * NC) * DS * DI + d;

    float h[DS];
#pragma unroll
    for (int n = 0; n < DS; n++) h[n] = 0.f;

    for (int c = 0; c < NC; c++) {
        float sdt = g_sumdt[base_sd + (long)c * DI];
#pragma unroll
        for (int n = 0; n < DS; n++) {
            long idx = base_S + ((long)c * DS + n) * DI;
            g_H0[idx] = h[n];
            h[n] = fmaf(__expf(An[n] * sdt), h[n], g_S[idx]);
        }
    }
}

// pass 3: re-run chunks with real h0, emit y
__global__ __launch_bounds__(256)
void scan_p3(const float* __restrict__ A_log0, const float* __restrict__ A_log1,
             const float* __restrict__ Dsk0,   const float* __restrict__ Dsk1)
{
    __shared__ float BC[CL][32];
    const int blk = blockIdx.x;
    const int dq  = blk & 3;
    const int c   = (blk >> 2) & (NC - 1);
    const int b   = (blk >> 7) & 1;
    const int dir = blk >> 8;
    const int d   = dq * 256 + threadIdx.x;

    const float* dbp = g_dbc[dir] + ((long)b * Lv + c * CL) * XPN;
    for (int i = threadIdx.x; i < CL * 32; i += 256)
        BC[i >> 5][i & 31] = dbp[(long)(i >> 5) * XPN + DTR + (i & 31)];
    __syncthreads();

    const float* A_log = dir ? A_log1 : A_log0;
    const float* Dsk   = dir ? Dsk1 : Dsk0;
    float An[DS];
#pragma unroll
    for (int n = 0; n < DS; n++) An[n] = -__expf(A_log[d * DS + n]);
    float Dd = Dsk[d];

    const float* dtp = g_dt[dir] + ((long)b * Lv + c * CL) * DI + d;
    const float* xcp = g_xc[dir] + ((long)b * Lv + c * CL) * DI + d;
    const float* zp  = g_xz[dir] + ((long)b * Lv + c * CL) * (2 * DI) + DI + d;
    float* yp        = g_ys[dir] + ((long)b * Lv + c * CL) * DI + d;

    long hb = (((long)(dir * Bv + b) * NC + c) * DS) * DI + d;
    float h[DS];
#pragma unroll
    for (int n = 0; n < DS; n++) h[n] = g_H0[hb + (long)n * DI];

    for (int l = 0; l < CL; l++) {
        float dt = dtp[l * DI];
        float xc = xcp[l * DI];
        float zv = zp[l * 2 * DI];
        float dx = dt * xc;
        float y = xc * Dd;
#pragma unroll
        for (int n = 0; n < DS; n++) {
            h[n] = fmaf(__expf(dt * An[n]), h[n], dx * BC[l][n]);
            y = fmaf(h[n], BC[l][DS + n], y);
        }
        yp[l * DI] = y * silu_f(zv);
    }
}

// ---------------- launch ----------------
extern "C" void kernel_launch(void* const* d_in, const int* in_sizes, int n_in,
                              void* d_out, int out_size)
{
    const float* hidden = (const float*)d_in[0];
    float* out = (float*)d_out;

    float *xz, *xc, *dbc, *dtb, *ys, *od, *wT;
    cudaGetSymbolAddress((void**)&xz,  g_xz);
    cudaGetSymbolAddress((void**)&xc,  g_xc);
    cudaGetSymbolAddress((void**)&dbc, g_dbc);
    cudaGetSymbolAddress((void**)&dtb, g_dt);
    cudaGetSymbolAddress((void**)&ys,  g_ys);
    cudaGetSymbolAddress((void**)&od,  g_od);
    cudaGetSymbolAddress((void**)&wT,  g_wT);

    const float* p[2][9];
    for (int dir = 0; dir < 2; dir++)
        for (int k = 0; k < 9; k++)
            p[dir][k] = (const float*)d_in[1 + 9 * dir + k];
    const float* fuse_w = (const float*)d_in[19];
    const float* fuse_b = (const float*)d_in[20];

    const long SXZ = (long)ROWS * 2 * DI, SXC = (long)ROWS * DI;
    const long SDB = (long)ROWS * XPN;

    const dim3 tb(32, 8);
    for (int dir = 0; dir < 2; dir++) {
        transpose_cvt<<<dim3(512 / 32, 2048 / 32), tb>>>(p[dir][0], wT + WT_IN(dir),  512, 2048);
        transpose_cvt<<<dim3(1024 / 32, 64 / 32),  tb>>>(p[dir][3], wT + WT_XP(dir),  1024, 64);
        transpose_cvt<<<dim3(32 / 32, 1024 / 32),  tb>>>(p[dir][4], wT + WT_DT(dir),  32, 1024);
        transpose_cvt<<<dim3(1024 / 32, 512 / 32), tb>>>(p[dir][8], wT + WT_OUT(dir), 1024, 512);
    }
    transpose_cvt<<<dim3(1024 / 32, 512 / 32), tb>>>(fuse_w, wT + WT_FUSE, 1024, 512);

    // 1. in_proj (bwd reads rows reversed)
    gemm_mma<128, 0><<<dim3(16, 32, 2), 256>>>(
        hidden, hidden, wT + WT_IN(0), wT + WT_IN(1), nullptr, nullptr,
        xz, xz + SXZ, DM, DM, 2 * DI, 0b10, 0);

    // 2. conv + silu
    conv_silu_kernel<<<(2 * ROWS * DI) / 256, 256>>>(p[0][1], p[0][2], p[1][1], p[1][2]);

    // 3. xproj
    gemm_mma<64, 0><<<dim3(1, 32, 2), 256>>>(
        xc, xc + SXC, wT + WT_XP(0), wT + WT_XP(1), nullptr, nullptr,
        dbc, dbc + SDB, DI, DI, XPN, 0, 0);

    // 4. dt proj + softplus
    gemm_mma<128, 1><<<dim3(8, 32, 2), 256>>>(
        dbc, dbc + SDB, wT + WT_DT(0), wT + WT_DT(1), p[0][5], p[1][5],
        dtb, dtb + SXC, DTR, XPN, DI, 0, 0);

    // 5. coalesced chunked scan
    scan_p1<<<2 * Bv * NC * (DI / 256), 256>>>(p[0][6], p[1][6]);
    scan_p2<<<(2 * Bv * DI) / 256, 256>>>(p[0][6], p[1][6]);
    scan_p3<<<2 * Bv * NC * (DI / 256), 256>>>(p[0][6], p[1][6], p[0][7], p[1][7]);

    // 6. out_proj -> od interleaved; bwd writes rows reversed
    gemm_mma<128, 0><<<dim3(4, 32, 2), 256>>>(
        ys, ys + SXC, wT + WT_OUT(0), wT + WT_OUT(1), nullptr, nullptr,
        od, od + DM, DI, DI, 2 * DM, 0, 0b10);

    // 7. fuse
    gemm_mma<128, 0><<<dim3(4, 32, 1), 256>>>(
        od, od, wT + WT_FUSE, wT + WT_FUSE, fuse_b, fuse_b,
        out, out, 2 * DM, 2 * DM, DM, 0, 0);
}

// round 7
// speedup vs baseline: 4.8164x; 1.0081x over previous
#include <cuda_runtime.h>
#include <cstdint>
#include <math.h>

#define Bv   2
#define Lv   2048
#define DM   512
#define DI   1024
#define DS   16
#define DTR  32
#define ROWS (Bv * Lv)      // 4096
#define XPN  (DTR + 2*DS)   // 64
#define NC   32
#define CL   (Lv / NC)      // 64

// ---------------- scratch ----------------
__device__ float g_xz [2][ROWS * 2 * DI];
__device__ float g_xc [2][ROWS * DI];
__device__ float g_dbc[2][ROWS * XPN];
__device__ float g_dt [2][ROWS * DI];
__device__ float g_ys2[ROWS * 2 * DI];             // [row][dir*1024 + d], bwd rows pre-reversed
__device__ float g_sumdt[2 * Bv * NC * DI];
__device__ float g_S    [2 * Bv * NC * DS * DI];
__device__ float g_H0   [2 * Bv * NC * DS * DI];
__device__ float g_wcomb[DM * 2 * DI];             // combined weight [n=512][k=2048]
// weight scratch, layout [N,K] (tf32-rounded)
#define WT_IN(dir)    ((long)(dir) * 1048576)
#define WT_XP(dir)    (2097152 + (long)(dir) * 65536)
#define WT_DT(dir)    (2228224 + (long)(dir) * 32768)
#define WT_FUSE       (2293760)
#define WR_OUT(dir)   (2818048 + (long)(dir) * 524288)   // out_w rounded, NOT transposed
__device__ float g_wT[3866624];

__device__ __forceinline__ float silu_f(float x) { return x / (1.f + __expf(-x)); }
__device__ __forceinline__ float tf32r(float x) {
    float r; asm("cvt.rna.tf32.f32 %0, %1;" : "=f"(r) : "f"(x)); return r;
}

// warp-level tf32 MMA (family-portable PTX, sm_80+)
__device__ __forceinline__ void mma8(float d[4], const float a[4], const float b[2]) {
    asm volatile("mma.sync.aligned.m16n8k8.row.col.f32.tf32.tf32.f32 "
        "{%0,%1,%2,%3}, {%4,%5,%6,%7}, {%8,%9}, {%0,%1,%2,%3};"
        : "+f"(d[0]), "+f"(d[1]), "+f"(d[2]), "+f"(d[3])
        : "r"(__float_as_uint(a[0])), "r"(__float_as_uint(a[1])),
          "r"(__float_as_uint(a[2])), "r"(__float_as_uint(a[3])),
          "r"(__float_as_uint(b[0])), "r"(__float_as_uint(b[1])));
}
__device__ __forceinline__ void cp16(uint32_t s, const void* g) {
    asm volatile("cp.async.ca.shared.global [%0], [%1], 16;" :: "r"(s), "l"(g));
}
#define CP_COMMIT() asm volatile("cp.async.commit_group;" ::: "memory")
#define CP_WAIT0()  asm volatile("cp.async.wait_group 0;" ::: "memory")

// ---------------- weight transpose + tf32 round ----------------
__global__ void transpose_cvt(const float* __restrict__ in, float* __restrict__ outp,
                              int K, int N)
{
    __shared__ float t[32][33];
    int k0 = blockIdx.x * 32, n0 = blockIdx.y * 32;
    int x = threadIdx.x, y = threadIdx.y;
#pragma unroll
    for (int i = 0; i < 32; i += 8)
        t[y + i][x] = in[(long)(k0 + y + i) * N + n0 + x];
    __syncthreads();
#pragma unroll
    for (int i = 0; i < 32; i += 8)
        outp[(long)(n0 + y + i) * K + k0 + x] = tf32r(t[x][y + i]);
}

// ---------------- elementwise tf32 round copy (both dirs) ----------------
__global__ void round_cvt2(const float* __restrict__ a0, const float* __restrict__ a1,
                           float* __restrict__ o0, float* __restrict__ o1, int n)
{
    int i = blockIdx.x * 256 + threadIdx.x;
    int dir = i >= n;
    int j = i - dir * n;
    const float* a = dir ? a1 : a0;
    float* o = dir ? o1 : o0;
    o[j] = tf32r(a[j]);
}

// ================= tf32 mma.sync GEMM: C[M,N] = A[M,K] @ Wt[N,K]^T =================
// EPI: 0 none, 1 softplus, 2 tf32-round
template<int NT, int EPI>
__global__ __launch_bounds__(256, 2)
void gemm_mma(const float* __restrict__ A0, const float* __restrict__ A1,
              const float* __restrict__ W0, const float* __restrict__ W1,
              const float* __restrict__ b0, const float* __restrict__ b1,
              float* __restrict__ C0, float* __restrict__ C1,
              int K, int lda, int ldc, int revAmask)
{
    constexpr int WN = NT / 2;
    constexpr int NTILES = WN / 8;
    constexpr int BJ = NT / 64;
    __shared__ float As[2][128][20];
    __shared__ float Ws[2][NT][20];
    constexpr uint32_t WBUF = NT * 20 * 4;

    const int tid = threadIdx.x;
    const int wid = tid >> 5, lane = tid & 31;
    const int wm = wid & 3, wn = wid >> 2;
    const int g = lane >> 2, t = lane & 3;

    const int dir = blockIdx.z;
    const float* A = dir ? A1 : A0;
    const float* W = dir ? W1 : W0;
    const float* bias = dir ? b1 : b0;
    float* C = dir ? C1 : C0;
    const int revA = (revAmask >> dir) & 1;
    const long m0 = (long)blockIdx.y * 128;
    const int n0 = blockIdx.x * NT;

    const float* aptr[2]; int asr[2], asq[2];
#pragma unroll
    for (int j = 0; j < 2; j++) {
        int qi = tid + j * 256;
        int row = qi >> 2, q = qi & 3;
        long arow = m0 + row;
        if (revA) { long bb = arow >> 11, l = arow & 2047; arow = (bb << 11) + (2047 - l); }
        aptr[j] = A + arow * lda + q * 4;
        asr[j] = row; asq[j] = q;
    }
    const float* bptr[BJ]; uint32_t bsw[BJ];
#pragma unroll
    for (int j = 0; j < BJ; j++) {
        int qi = tid + j * 256;
        int row = qi >> 2, q = qi & 3;
        bptr[j] = W + (long)(n0 + row) * K + q * 4;
        bsw[j] = (uint32_t)__cvta_generic_to_shared(&Ws[0][row][q * 4]);
    }

    float acc[2][NTILES][4];
#pragma unroll
    for (int i = 0; i < 2; i++)
#pragma unroll
        for (int j = 0; j < NTILES; j++)
#pragma unroll
            for (int e = 0; e < 4; e++) acc[i][j][e] = 0.f;

    const int nb = K >> 4;
    float4 ra[2];

    // stage 0
#pragma unroll
    for (int j = 0; j < BJ; j++) cp16(bsw[j], bptr[j]);
    CP_COMMIT();
#pragma unroll
    for (int j = 0; j < 2; j++) ra[j] = *(const float4*)(aptr[j]);
#pragma unroll
    for (int j = 0; j < 2; j++) {
        float4 v = ra[j];
        v.x = tf32r(v.x); v.y = tf32r(v.y); v.z = tf32r(v.z); v.w = tf32r(v.w);
        *(float4*)&As[0][asr[j]][asq[j] * 4] = v;
    }
    CP_WAIT0();
    __syncthreads();

    for (int s = 0; s < nb; s++) {
        const int buf = s & 1;
        const bool more = (s + 1 < nb);
        if (more) {
            const int ko = (s + 1) * 16;
#pragma unroll
            for (int j = 0; j < BJ; j++) cp16(bsw[j] + (buf ^ 1) * WBUF, bptr[j] + ko);
            CP_COMMIT();
#pragma unroll
            for (int j = 0; j < 2; j++) ra[j] = *(const float4*)(aptr[j] + ko);
        }
#pragma unroll
        for (int kk = 0; kk < 2; kk++) {
            float afr[2][4];
#pragma unroll
            for (int mt = 0; mt < 2; mt++) {
                int r = wm * 32 + mt * 16;
                afr[mt][0] = As[buf][r + g     ][kk * 8 + t];
                afr[mt][1] = As[buf][r + g + 8 ][kk * 8 + t];
                afr[mt][2] = As[buf][r + g     ][kk * 8 + t + 4];
                afr[mt][3] = As[buf][r + g + 8 ][kk * 8 + t + 4];
            }
#pragma unroll
            for (int nt = 0; nt < NTILES; nt++) {
                int nc = wn * WN + nt * 8;
                float bfr[2];
                bfr[0] = Ws[buf][nc + g][kk * 8 + t];
                bfr[1] = Ws[buf][nc + g][kk * 8 + t + 4];
                mma8(acc[0][nt], afr[0], bfr);
                mma8(acc[1][nt], afr[1], bfr);
            }
        }
        if (more) {
            const int nbuf = buf ^ 1;
#pragma unroll
            for (int j = 0; j < 2; j++) {
                float4 v = ra[j];
                v.x = tf32r(v.x); v.y = tf32r(v.y); v.z = tf32r(v.z); v.w = tf32r(v.w);
                *(float4*)&As[nbuf][asr[j]][asq[j] * 4] = v;
            }
            CP_WAIT0();
            __syncthreads();
        }
    }

#pragma unroll
    for (int mt = 0; mt < 2; mt++) {
#pragma unroll
        for (int half = 0; half < 2; half++) {
            long row = m0 + wm * 32 + mt * 16 + g + half * 8;
            float* Cp = C + row * ldc + n0 + wn * WN;
#pragma unroll
            for (int nt = 0; nt < NTILES; nt++) {
                int col = nt * 8 + 2 * t;
                float2 v;
                v.x = acc[mt][nt][half * 2 + 0];
                v.y = acc[mt][nt][half * 2 + 1];
                if (bias) {
                    v.x += bias[n0 + wn * WN + col];
                    v.y += bias[n0 + wn * WN + col + 1];
                }
                if (EPI == 1) {
                    v.x = (v.x > 20.f) ? v.x : log1pf(__expf(v.x));
                    v.y = (v.y > 20.f) ? v.y : log1pf(__expf(v.y));
                }
                if (EPI == 2) { v.x = tf32r(v.x); v.y = tf32r(v.y); }
                *(float2*)(Cp + col) = v;
            }
        }
    }
}

// ---------------- depthwise causal conv + SiLU ----------------
__global__ void conv_silu_kernel(const float* __restrict__ cw0, const float* __restrict__ cb0,
                                 const float* __restrict__ cw1, const float* __restrict__ cb1)
{
    int idx = blockIdx.x * blockDim.x + threadIdx.x;
    int dir = idx >= ROWS * DI;
    int rem = idx - dir * ROWS * DI;
    const float* cw = dir ? cw1 : cw0;
    const float* cb = dir ? cb1 : cb0;
    const float* xz = g_xz[dir];
    float* xc = g_xc[dir];

    int d   = rem & (DI - 1);
    int row = rem >> 10;
    int l   = row & (Lv - 1);
    float s = cb[d];
    float w0 = cw[d * 4 + 0], w1 = cw[d * 4 + 1],
          w2 = cw[d * 4 + 2], w3 = cw[d * 4 + 3];
    const float* xp = xz + (long)row * (2 * DI) + d;
    if (l >= 3) s = fmaf(w0, xp[-3 * 2 * DI], s);
    if (l >= 2) s = fmaf(w1, xp[-2 * 2 * DI], s);
    if (l >= 1) s = fmaf(w2, xp[-1 * 2 * DI], s);
    s = fmaf(w3, xp[0], s);
    xc[rem] = silu_f(s);
}

// ================= coalesced chunked scan =================
__global__ __launch_bounds__(256)
void scan_p1(const float* __restrict__ A_log0, const float* __restrict__ A_log1)
{
    __shared__ float BC[CL][32];
    const int blk = blockIdx.x;
    const int dq  = blk & 3;
    const int c   = (blk >> 2) & (NC - 1);
    const int b   = (blk >> 7) & 1;
    const int dir = blk >> 8;
    const int d   = dq * 256 + threadIdx.x;

    const float* dbp = g_dbc[dir] + ((long)b * Lv + c * CL) * XPN;
    for (int i = threadIdx.x; i < CL * 32; i += 256)
        BC[i >> 5][i & 31] = dbp[(long)(i >> 5) * XPN + DTR + (i & 31)];
    __syncthreads();

    const float* A_log = dir ? A_log1 : A_log0;
    float An[DS];
#pragma unroll
    for (int n = 0; n < DS; n++) An[n] = -__expf(A_log[d * DS + n]);

    const float* dtp = g_dt[dir] + ((long)b * Lv + c * CL) * DI + d;
    const float* xcp = g_xc[dir] + ((long)b * Lv + c * CL) * DI + d;

    float h[DS];
#pragma unroll
    for (int n = 0; n < DS; n++) h[n] = 0.f;
    float sdt = 0.f;

    for (int l = 0; l < CL; l++) {
        float dt = dtp[l * DI];
        float xc = xcp[l * DI];
        float dx = dt * xc;
        sdt += dt;
#pragma unroll
        for (int n = 0; n < DS; n++)
            h[n] = fmaf(__expf(dt * An[n]), h[n], dx * BC[l][n]);
    }

    long sb = (((long)(dir * Bv + b) * NC + c) * DS) * DI + d;
#pragma unroll
    for (int n = 0; n < DS; n++) g_S[sb + (long)n * DI] = h[n];
    g_sumdt[((long)(dir * Bv + b) * NC + c) * DI + d] = sdt;
}

__global__ __launch_bounds__(256)
void scan_p2(const float* __restrict__ A_log0, const float* __restrict__ A_log1)
{
    int t = blockIdx.x * 256 + threadIdx.x;
    int d   = t & (DI - 1);
    int b   = (t >> 10) & 1;
    int dir = t >> 11;

    const float* A_log = dir ? A_log1 : A_log0;
    float An[DS];
#pragma unroll
    for (int n = 0; n < DS; n++) An[n] = -__expf(A_log[d * DS + n]);

    long base_sd = ((long)(dir * Bv + b) * NC) * DI + d;
    long base_S  = ((long)(dir * Bv + b) * NC) * DS * DI + d;

    float h[DS];
#pragma unroll
    for (int n = 0; n < DS; n++) h[n] = 0.f;

    for (int c = 0; c < NC; c++) {
        float sdt = g_sumdt[base_sd + (long)c * DI];
#pragma unroll
        for (int n = 0; n < DS; n++) {
            long idx = base_S + ((long)c * DS + n) * DI;
            g_H0[idx] = h[n];
            h[n] = fmaf(__expf(An[n] * sdt), h[n], g_S[idx]);
        }
    }
}

// pass 3: re-run chunks with real h0, emit y into g_ys2 (bwd rows reversed)
__global__ __launch_bounds__(256)
void scan_p3(const float* __restrict__ A_log0, const float* __restrict__ A_log1,
             const float* __restrict__ Dsk0,   const float* __restrict__ Dsk1)
{
    __shared__ float BC[CL][32];
    const int blk = blockIdx.x;
    const int dq  = blk & 3;
    const int c   = (blk >> 2) & (NC - 1);
    const int b   = (blk >> 7) & 1;
    const int dir = blk >> 8;
    const int d   = dq * 256 + threadIdx.x;

    const float* dbp = g_dbc[dir] + ((long)b * Lv + c * CL) * XPN;
    for (int i = threadIdx.x; i < CL * 32; i += 256)
        BC[i >> 5][i & 31] = dbp[(long)(i >> 5) * XPN + DTR + (i & 31)];
    __syncthreads();

    const float* A_log = dir ? A_log1 : A_log0;
    const float* Dsk   = dir ? Dsk1 : Dsk0;
    float An[DS];
#pragma unroll
    for (int n = 0; n < DS; n++) An[n] = -__expf(A_log[d * DS + n]);
    float Dd = Dsk[d];

    const float* dtp = g_dt[dir] + ((long)b * Lv + c * CL) * DI + d;
    const float* xcp = g_xc[dir] + ((long)b * Lv + c * CL) * DI + d;
    const float* zp  = g_xz[dir] + ((long)b * Lv + c * CL) * (2 * DI) + DI + d;

    long hb = (((long)(dir * Bv + b) * NC + c) * DS) * DI + d;
    float h[DS];
#pragma unroll
    for (int n = 0; n < DS; n++) h[n] = g_H0[hb + (long)n * DI];

    for (int l = 0; l < CL; l++) {
        float dt = dtp[l * DI];
        float xc = xcp[l * DI];
        float zv = zp[l * 2 * DI];
        float dx = dt * xc;
        float y = xc * Dd;
#pragma unroll
        for (int n = 0; n < DS; n++) {
            h[n] = fmaf(__expf(dt * An[n]), h[n], dx * BC[l][n]);
            y = fmaf(h[n], BC[l][DS + n], y);
        }
        int lrow = c * CL + l;
        if (dir) lrow = Lv - 1 - lrow;            // bwd: store reversed
        g_ys2[((long)b * Lv + lrow) * (2 * DI) + dir * DI + d] = y * silu_f(zv);
    }
}

// ---------------- launch ----------------
extern "C" void kernel_launch(void* const* d_in, const int* in_sizes, int n_in,
                              void* d_out, int out_size)
{
    const float* hidden = (const float*)d_in[0];
    float* out = (float*)d_out;

    float *xz, *xc, *dbc, *dtb, *ys2, *wT, *wcomb;
    cudaGetSymbolAddress((void**)&xz,    g_xz);
    cudaGetSymbolAddress((void**)&xc,    g_xc);
    cudaGetSymbolAddress((void**)&dbc,   g_dbc);
    cudaGetSymbolAddress((void**)&dtb,   g_dt);
    cudaGetSymbolAddress((void**)&ys2,   g_ys2);
    cudaGetSymbolAddress((void**)&wT,    g_wT);
    cudaGetSymbolAddress((void**)&wcomb, g_wcomb);

    const float* p[2][9];
    for (int dir = 0; dir < 2; dir++)
        for (int k = 0; k < 9; k++)
            p[dir][k] = (const float*)d_in[1 + 9 * dir + k];
    const float* fuse_w = (const float*)d_in[19];
    const float* fuse_b = (const float*)d_in[20];

    const long SXZ = (long)ROWS * 2 * DI, SXC = (long)ROWS * DI;
    const long SDB = (long)ROWS * XPN;

    const dim3 tb(32, 8);
    for (int dir = 0; dir < 2; dir++) {
        transpose_cvt<<<dim3(512 / 32, 2048 / 32), tb>>>(p[dir][0], wT + WT_IN(dir),  512, 2048);
        transpose_cvt<<<dim3(1024 / 32, 64 / 32),  tb>>>(p[dir][3], wT + WT_XP(dir),  1024, 64);
        transpose_cvt<<<dim3(32 / 32, 1024 / 32),  tb>>>(p[dir][4], wT + WT_DT(dir),  32, 1024);
    }
    transpose_cvt<<<dim3(1024 / 32, 512 / 32), tb>>>(fuse_w, wT + WT_FUSE, 1024, 512);
    round_cvt2<<<(2 * 1024 * 512) / 256, 256>>>(p[0][8], p[1][8],
                                                wT + WR_OUT(0), wT + WR_OUT(1), 1024 * 512);

    // Precompute combined weight: wcomb[n][dir*1024+kk] = sum_j fuse^T[n][dir*512+j] * out_w[kk][j]
    gemm_mma<128, 2><<<dim3(8, 4, 2), 256>>>(
        wT + WT_FUSE, wT + WT_FUSE + DM, wT + WR_OUT(0), wT + WR_OUT(1),
        nullptr, nullptr, wcomb, wcomb + DI, DM, 2 * DM, 2 * DI, 0);

    // 1. in_proj (bwd reads rows reversed)
    gemm_mma<128, 0><<<dim3(16, 32, 2), 256>>>(
        hidden, hidden, wT + WT_IN(0), wT + WT_IN(1), nullptr, nullptr,
        xz, xz + SXZ, DM, DM, 2 * DI, 0b10);

    // 2. conv + silu
    conv_silu_kernel<<<(2 * ROWS * DI) / 256, 256>>>(p[0][1], p[0][2], p[1][1], p[1][2]);

    // 3. xproj
    gemm_mma<64, 0><<<dim3(1, 32, 2), 256>>>(
        xc, xc + SXC, wT + WT_XP(0), wT + WT_XP(1), nullptr, nullptr,
        dbc, dbc + SDB, DI, DI, XPN, 0);

    // 4. dt proj + softplus
    gemm_mma<128, 1><<<dim3(8, 32, 2), 256>>>(
        dbc, dbc + SDB, wT + WT_DT(0), wT + WT_DT(1), p[0][5], p[1][5],
        dtb, dtb + SXC, DTR, XPN, DI, 0);

    // 5. coalesced chunked scan -> g_ys2 (bwd reversed)
    scan_p1<<<2 * Bv * NC * (DI / 256), 256>>>(p[0][6], p[1][6]);
    scan_p2<<<(2 * Bv * DI) / 256, 256>>>(p[0][6], p[1][6]);
    scan_p3<<<2 * Bv * NC * (DI / 256), 256>>>(p[0][6], p[1][6], p[0][7], p[1][7]);

    // 6. single combined output GEMM: (4096,2048)@wcomb^T + fuse_b -> out
    gemm_mma<128, 0><<<dim3(4, 32, 1), 256>>>(
        ys2, ys2, wcomb, wcomb, fuse_b, fuse_b,
        out, out, 2 * DI, 2 * DI, DM, 0);
}